// round 8
// baseline (speedup 1.0000x reference)
#include <cuda_runtime.h>
#include <math.h>

#define BB 64
#define NN 256
#define DD 128
#define HH 8
#define FF 512
#define EPSV 1e-5

// ------- scratch (device globals; no allocations anywhere) -------
__device__ float g_Q[BB * NN * DD];
__device__ float g_K[BB * NN * DD];
__device__ float g_V[BB * NN * DD];
__device__ float g_attn[(size_t)BB * HH * NN * NN];
__device__ float g_M[BB * HH * NN];
__device__ float g_invL[BB * HH * NN];
__device__ float g_heads[BB * NN * DD];
__device__ float g_x0[BB * NN * DD];
__device__ float g_hdn[BB * NN * FF];
__device__ float g_y0[BB * NN * DD];
__device__ float g_ps[2][BB * 16];
__device__ float g_pq[2][BB * 16];
__device__ float g_mu[2][BB];
__device__ float g_iv[2][BB];

// ============ K1: Q/K/V projections (16 rows/block, 2x4 tile) ============
__global__ __launch_bounds__(256) void k1_qkv(const float* __restrict__ hem,
                                              const float* __restrict__ Wq,
                                              const float* __restrict__ Wk,
                                              const float* __restrict__ Wv) {
    __shared__ __align__(16) float ws[64 * 128];
    __shared__ float xs[16 * 128];
    int b = blockIdx.y, n0 = blockIdx.x * 16, t = threadIdx.x;
    for (int e = t; e < 2048; e += 256)
        xs[e] = hem[((size_t)b * NN + n0) * DD + e];
    int rg = t >> 5, c4 = (t & 31) * 4;
    for (int wi = 0; wi < 3; wi++) {
        const float* W = (wi == 0) ? Wq : (wi == 1) ? Wk : Wv;
        float* O = (wi == 0) ? g_Q : (wi == 1) ? g_K : g_V;
        float acc[2][4] = {};
        for (int dc = 0; dc < 2; dc++) {
            __syncthreads();
            for (int e = t; e < 8192; e += 256) {
                int h = e >> 10, rem = e & 1023, dl = rem >> 4, k = rem & 15;
                ws[dl * 128 + h * 16 + k] = W[h * 2048 + (dc * 64 + dl) * 16 + k];
            }
            __syncthreads();
#pragma unroll 8
            for (int dl = 0; dl < 64; dl++) {
                int d = dc * 64 + dl;
                float4 w = *(const float4*)&ws[dl * 128 + c4];
                float x0v = xs[rg * 128 + d], x1v = xs[(rg + 8) * 128 + d];
                acc[0][0] += x0v * w.x; acc[0][1] += x0v * w.y;
                acc[0][2] += x0v * w.z; acc[0][3] += x0v * w.w;
                acc[1][0] += x1v * w.x; acc[1][1] += x1v * w.y;
                acc[1][2] += x1v * w.z; acc[1][3] += x1v * w.w;
            }
        }
#pragma unroll
        for (int r = 0; r < 2; r++)
            *(float4*)&O[((size_t)b * NN + n0 + rg + r * 8) * DD + c4] =
                make_float4(acc[r][0], acc[r][1], acc[r][2], acc[r][3]);
    }
}

// ==== K2: scores + score_aggr MLP -> attn, online softmax stats ====
__global__ __launch_bounds__(256) void k2_attn(const float* __restrict__ route,
                                               const float* __restrict__ sw1,
                                               const float* __restrict__ sb1,
                                               const float* __restrict__ sw2,
                                               const float* __restrict__ sb2) {
    __shared__ float Qs[16 * 128];
    __shared__ float Ks[64 * 129];
    __shared__ float w1s[256], w2s[128], b1s[16], b2s[8];
    int b = blockIdx.y, n0 = blockIdx.x * 16, t = threadIdx.x;
    int warp = t >> 5, lane = t & 31;
    for (int e = t; e < 2048; e += 256)
        Qs[e] = g_Q[((size_t)b * NN + n0) * DD + e];
    w1s[t] = sw1[t];
    if (t < 128) w2s[t] = sw2[t];
    if (t < 16) b1s[t] = sb1[t];
    if (t < 8) b2s[t] = sb2[t];
    float M[2][8], L[2][8];
#pragma unroll
    for (int r = 0; r < 2; r++)
#pragma unroll
        for (int h = 0; h < 8; h++) { M[r][h] = -1e30f; L[r][h] = 0.f; }

#pragma unroll 1
    for (int mc = 0; mc < 4; mc++) {
        __syncthreads();
        for (int e = t; e < 8192; e += 256)
            Ks[(e >> 7) * 129 + (e & 127)] =
                g_K[((size_t)b * NN + mc * 64 + (e >> 7)) * DD + (e & 127)];
        __syncthreads();
#pragma unroll 1
        for (int r = 0; r < 2; r++) {
            int nl = warp + r * 8, n = n0 + nl, m0 = mc * 64 + lane;
            float s0[8] = {}, s1[8] = {};
#pragma unroll
            for (int h = 0; h < 8; h++)
#pragma unroll
                for (int k = 0; k < 16; k++) {
                    float q = Qs[nl * 128 + h * 16 + k];
                    s0[h] += q * Ks[lane * 129 + h * 16 + k];
                    s1[h] += q * Ks[(lane + 32) * 129 + h * 16 + k];
                }
            float r0[8], r1[8];
#pragma unroll
            for (int h = 0; h < 8; h++) {
                const float* rp = route + (((size_t)h * BB + b) * NN + n) * NN + m0;
                r0[h] = rp[0]; r1[h] = rp[32];
            }
            float hd0[16], hd1[16];
#pragma unroll
            for (int j = 0; j < 16; j++) { hd0[j] = b1s[j]; hd1[j] = b1s[j]; }
#pragma unroll
            for (int i = 0; i < 16; i++) {
                float xi0 = (i < 8) ? s0[i] : r0[i - 8];
                float xi1 = (i < 8) ? s1[i] : r1[i - 8];
#pragma unroll
                for (int j = 0; j < 16; j++) {
                    float w = w1s[i * 16 + j];
                    hd0[j] += xi0 * w; hd1[j] += xi1 * w;
                }
            }
            float a0[8], a1[8];
#pragma unroll
            for (int h = 0; h < 8; h++) { a0[h] = b2s[h]; a1[h] = b2s[h]; }
#pragma unroll
            for (int j = 0; j < 16; j++) {
                float h0 = fmaxf(hd0[j], 0.f), h1 = fmaxf(hd1[j], 0.f);
#pragma unroll
                for (int h = 0; h < 8; h++) {
                    float w = w2s[j * 8 + h];
                    a0[h] += h0 * w; a1[h] += h1 * w;
                }
            }
#pragma unroll
            for (int h = 0; h < 8; h++) {
                float* ap = g_attn + (((size_t)b * HH + h) * NN + n) * NN + m0;
                ap[0] = a0[h]; ap[32] = a1[h];
                float cm = fmaxf(a0[h], a1[h]);
#pragma unroll
                for (int o = 16; o > 0; o >>= 1)
                    cm = fmaxf(cm, __shfl_xor_sync(0xffffffffu, cm, o));
                float nm = fmaxf(M[r][h], cm);
                float cs = __expf(a0[h] - nm) + __expf(a1[h] - nm);
#pragma unroll
                for (int o = 16; o > 0; o >>= 1)
                    cs += __shfl_xor_sync(0xffffffffu, cs, o);
                L[r][h] = L[r][h] * __expf(M[r][h] - nm) + cs;
                M[r][h] = nm;
            }
        }
    }
    if (lane == 0)
#pragma unroll
        for (int r = 0; r < 2; r++) {
            int n = n0 + warp + r * 8;
#pragma unroll
            for (int h = 0; h < 8; h++) {
                g_M[((size_t)b * HH + h) * NN + n] = M[r][h];
                g_invL[((size_t)b * HH + h) * NN + n] = 1.f / L[r][h];
            }
        }
}

// ============ K3: softmax probs + P @ V -> heads ============
__global__ __launch_bounds__(256) void k3_heads() {
    __shared__ float Vs[256 * 17];
    __shared__ float ps[32 * 33];
    __shared__ float Ms[32], Ls[32];
    int n0 = blockIdx.x * 32, h = blockIdx.y, b = blockIdx.z, t = threadIdx.x;
    for (int e = t; e < 4096; e += 256)
        Vs[(e >> 4) * 17 + (e & 15)] =
            g_V[((size_t)b * NN + (e >> 4)) * DD + h * 16 + (e & 15)];
    if (t < 32) {
        Ms[t] = g_M[((size_t)b * HH + h) * NN + n0 + t];
        Ls[t] = g_invL[((size_t)b * HH + h) * NN + n0 + t];
    }
    __syncthreads();
    int n_t = t >> 3, vb = (t & 7) * 2;
    float a0 = 0.f, a1 = 0.f;
#pragma unroll 1
    for (int mc = 0; mc < 8; mc++) {
#pragma unroll
        for (int i = 0; i < 4; i++) {
            int e = t + i * 256, nl = e >> 5, ml = e & 31;
            float a = g_attn[(((size_t)b * HH + h) * NN + n0 + nl) * NN + mc * 32 + ml];
            ps[nl * 33 + ml] = __expf(a - Ms[nl]) * Ls[nl];
        }
        __syncthreads();
#pragma unroll
        for (int ml = 0; ml < 32; ml++) {
            float p = ps[n_t * 33 + ml];
            int m = mc * 32 + ml;
            a0 += p * Vs[m * 17 + vb];
            a1 += p * Vs[m * 17 + vb + 1];
        }
        __syncthreads();
    }
    size_t o = ((size_t)b * NN + n0 + n_t) * DD + h * 16 + vb;
    g_heads[o] = a0; g_heads[o + 1] = a1;
}

// ============ K4: heads @ W_out + h_em -> x0, LN partials[0] ============
__global__ __launch_bounds__(256) void k4_out(const float* __restrict__ Wo,
                                              const float* __restrict__ hem) {
    __shared__ __align__(16) float ws[64 * 128];
    __shared__ float hs[16 * 128];
    __shared__ float red[16];
    int b = blockIdx.y, n0 = blockIdx.x * 16, t = threadIdx.x;
    int warp = t >> 5, lane = t & 31;
    for (int e = t; e < 2048; e += 256)
        hs[e] = g_heads[((size_t)b * NN + n0) * DD + e];
    int rg = warp, c4 = lane * 4;
    float acc[2][4] = {};
    for (int jc = 0; jc < 2; jc++) {
        __syncthreads();
        for (int e = t; e < 8192; e += 256) ws[e] = Wo[jc * 8192 + e];
        __syncthreads();
#pragma unroll 8
        for (int jl = 0; jl < 64; jl++) {
            float4 w = *(const float4*)&ws[jl * 128 + c4];
            float h0 = hs[rg * 128 + jc * 64 + jl], h1 = hs[(rg + 8) * 128 + jc * 64 + jl];
            acc[0][0] += h0 * w.x; acc[0][1] += h0 * w.y;
            acc[0][2] += h0 * w.z; acc[0][3] += h0 * w.w;
            acc[1][0] += h1 * w.x; acc[1][1] += h1 * w.y;
            acc[1][2] += h1 * w.z; acc[1][3] += h1 * w.w;
        }
    }
    float ls = 0.f, lq = 0.f;
#pragma unroll
    for (int r = 0; r < 2; r++) {
        size_t base = ((size_t)b * NN + n0 + rg + r * 8) * DD + c4;
        float4 he = *(const float4*)&hem[base];
        float v0 = acc[r][0] + he.x, v1 = acc[r][1] + he.y;
        float v2 = acc[r][2] + he.z, v3 = acc[r][3] + he.w;
        *(float4*)&g_x0[base] = make_float4(v0, v1, v2, v3);
        ls += v0 + v1 + v2 + v3;
        lq += v0 * v0 + v1 * v1 + v2 * v2 + v3 * v3;
    }
#pragma unroll
    for (int o = 16; o > 0; o >>= 1) {
        ls += __shfl_xor_sync(0xffffffffu, ls, o);
        lq += __shfl_xor_sync(0xffffffffu, lq, o);
    }
    if (lane == 0) { red[warp] = ls; red[8 + warp] = lq; }
    __syncthreads();
    if (t == 0) {
        float s = 0.f, q = 0.f;
        for (int w = 0; w < 8; w++) { s += red[w]; q += red[8 + w]; }
        g_ps[0][b * 16 + blockIdx.x] = s;
        g_pq[0][b * 16 + blockIdx.x] = q;
    }
}

// ============ finalize LN stats (ddof=1) ============
__global__ void k_fin(int which) {
    int b = threadIdx.x;
    if (b < BB) {
        double s = 0.0, q = 0.0;
        for (int i = 0; i < 16; i++) {
            s += (double)g_ps[which][b * 16 + i];
            q += (double)g_pq[which][b * 16 + i];
        }
        double n = (double)(NN * DD);
        double mean = s / n;
        double var = (q - s * s / n) / (n - 1.0);
        g_mu[which][b] = (float)mean;
        g_iv[which][b] = (float)(1.0 / sqrt(var + EPSV));
    }
}

// ============ K6: x = LN(x0); hdn = relu(x @ ff_w1) ============
__global__ __launch_bounds__(256) void k6_ff1(const float* __restrict__ w1) {
    __shared__ __align__(16) float ws[64 * 128];
    __shared__ float xs[16 * 128];
    int b = blockIdx.y, n0 = blockIdx.x * 16, t = threadIdx.x;
    float mu = g_mu[0][b], iv = g_iv[0][b];
    for (int e = t; e < 2048; e += 256)
        xs[e] = (g_x0[((size_t)b * NN + n0) * DD + e] - mu) * iv;
    int rg = t >> 5, f4 = (t & 31) * 4;
    for (int ft = 0; ft < 4; ft++) {
        float acc[2][4] = {};
        for (int dc = 0; dc < 2; dc++) {
            __syncthreads();
            for (int e = t; e < 8192; e += 256)
                ws[e] = w1[(dc * 64 + (e >> 7)) * FF + ft * 128 + (e & 127)];
            __syncthreads();
#pragma unroll 8
            for (int dl = 0; dl < 64; dl++) {
                int d = dc * 64 + dl;
                float4 w = *(const float4*)&ws[dl * 128 + f4];
                float x0v = xs[rg * 128 + d], x1v = xs[(rg + 8) * 128 + d];
                acc[0][0] += x0v * w.x; acc[0][1] += x0v * w.y;
                acc[0][2] += x0v * w.z; acc[0][3] += x0v * w.w;
                acc[1][0] += x1v * w.x; acc[1][1] += x1v * w.y;
                acc[1][2] += x1v * w.z; acc[1][3] += x1v * w.w;
            }
        }
#pragma unroll
        for (int r = 0; r < 2; r++)
            *(float4*)&g_hdn[((size_t)b * NN + n0 + rg + r * 8) * FF + ft * 128 + f4] =
                make_float4(fmaxf(acc[r][0], 0.f), fmaxf(acc[r][1], 0.f),
                            fmaxf(acc[r][2], 0.f), fmaxf(acc[r][3], 0.f));
    }
}

// ============ K7: y0 = hdn @ ff_w2 + x, LN partials[1] ============
__global__ __launch_bounds__(256) void k7_ff2(const float* __restrict__ w2) {
    __shared__ __align__(16) float ws[64 * 128];
    __shared__ float hsm[16 * 64];
    __shared__ float red[16];
    int b = blockIdx.y, n0 = blockIdx.x * 16, t = threadIdx.x;
    int warp = t >> 5, lane = t & 31;
    int rg = warp, d4 = lane * 4;
    float acc[2][4] = {};
    for (int kc = 0; kc < 8; kc++) {
        __syncthreads();
        for (int e = t; e < 8192; e += 256) ws[e] = w2[kc * 8192 + e];
        for (int e = t; e < 1024; e += 256)
            hsm[e] = g_hdn[((size_t)b * NN + n0 + (e >> 6)) * FF + kc * 64 + (e & 63)];
        __syncthreads();
#pragma unroll 8
        for (int kl = 0; kl < 64; kl++) {
            float4 w = *(const float4*)&ws[kl * 128 + d4];
            float h0 = hsm[rg * 64 + kl], h1 = hsm[(rg + 8) * 64 + kl];
            acc[0][0] += h0 * w.x; acc[0][1] += h0 * w.y;
            acc[0][2] += h0 * w.z; acc[0][3] += h0 * w.w;
            acc[1][0] += h1 * w.x; acc[1][1] += h1 * w.y;
            acc[1][2] += h1 * w.z; acc[1][3] += h1 * w.w;
        }
    }
    float mu = g_mu[0][b], iv = g_iv[0][b];
    float ls = 0.f, lq = 0.f;
#pragma unroll
    for (int r = 0; r < 2; r++) {
        size_t base = ((size_t)b * NN + n0 + rg + r * 8) * DD + d4;
        float4 xv = *(const float4*)&g_x0[base];
        float v0 = acc[r][0] + (xv.x - mu) * iv;
        float v1 = acc[r][1] + (xv.y - mu) * iv;
        float v2 = acc[r][2] + (xv.z - mu) * iv;
        float v3 = acc[r][3] + (xv.w - mu) * iv;
        *(float4*)&g_y0[base] = make_float4(v0, v1, v2, v3);
        ls += v0 + v1 + v2 + v3;
        lq += v0 * v0 + v1 * v1 + v2 * v2 + v3 * v3;
    }
#pragma unroll
    for (int o = 16; o > 0; o >>= 1) {
        ls += __shfl_xor_sync(0xffffffffu, ls, o);
        lq += __shfl_xor_sync(0xffffffffu, lq, o);
    }
    if (lane == 0) { red[warp] = ls; red[8 + warp] = lq; }
    __syncthreads();
    if (t == 0) {
        float s = 0.f, q = 0.f;
        for (int w = 0; w < 8; w++) { s += red[w]; q += red[8 + w]; }
        g_ps[1][b * 16 + blockIdx.x] = s;
        g_pq[1][b * 16 + blockIdx.x] = q;
    }
}

// ============ K8: out1 = LN(y0) ============
__global__ __launch_bounds__(256) void k8_norm(float* __restrict__ out) {
    int i = blockIdx.x * 256 + threadIdx.x;   // 524288 float4
    int b = i >> 13;
    float mu = g_mu[1][b], iv = g_iv[1][b];
    float4 v = ((const float4*)g_y0)[i];
    v.x = (v.x - mu) * iv; v.y = (v.y - mu) * iv;
    v.z = (v.z - mu) * iv; v.w = (v.w - mu) * iv;
    ((float4*)out)[i] = v;
}

// ============ launcher ============
extern "C" void kernel_launch(void* const* d_in, const int* in_sizes, int n_in,
                              void* d_out, int out_size) {
    const float* hem = (const float*)d_in[0];
    const float* route = (const float*)d_in[1];
    const float* Wq = (const float*)d_in[2];
    const float* Wk = (const float*)d_in[3];
    const float* Wv = (const float*)d_in[4];
    const float* Wo = (const float*)d_in[5];
    const float* sw1 = (const float*)d_in[6];
    const float* sb1 = (const float*)d_in[7];
    const float* sw2 = (const float*)d_in[8];
    const float* sb2 = (const float*)d_in[9];
    const float* fw1 = (const float*)d_in[10];
    const float* fw2 = (const float*)d_in[11];
    float* out = (float*)d_out;

    const long long OUT1 = (long long)BB * NN * DD;        // 2097152
    const long long ROUTE = (long long)HH * BB * NN * NN;  // 33554432

    dim3 g16(16, BB);
    dim3 g3(8, HH, BB);

    k1_qkv<<<g16, 256>>>(hem, Wq, Wk, Wv);
    k2_attn<<<g16, 256>>>(route, sw1, sb1, sw2, sb2);
    k3_heads<<<g3, 256>>>();
    k4_out<<<g16, 256>>>(Wo, hem);
    k_fin<<<1, 64>>>(0);
    k6_ff1<<<g16, 256>>>(fw1);
    k7_ff2<<<g16, 256>>>(fw2);
    k_fin<<<1, 64>>>(1);
    k8_norm<<<2048, 256>>>(out);

    if ((long long)out_size >= OUT1 + ROUTE) {
        cudaMemcpyAsync(out + OUT1, route, (size_t)ROUTE * sizeof(float),
                        cudaMemcpyDeviceToDevice);
    }
}

// round 11
// speedup vs baseline: 2.2599x; 2.2599x over previous
#include <cuda_runtime.h>
#include <math.h>

#define BB 64
#define NN 256
#define DD 128
#define HH 8
#define FF 512
#define EPSV 1e-5

// ------- scratch (device globals; no allocations anywhere) -------
__device__ float g_Q[BB * NN * DD];
__device__ float g_K[BB * NN * DD];
__device__ float g_V[BB * NN * DD];
__device__ float g_heads[BB * NN * DD];
__device__ float g_x0[BB * NN * DD];
__device__ float g_hdn[BB * NN * FF];
__device__ float g_y0[BB * NN * DD];
__device__ float g_ps[2][BB * 16];
__device__ float g_pq[2][BB * 16];
__device__ float g_mu[2][BB];
__device__ float g_iv[2][BB];

// select arr[idx] for idx in 0..7 without dynamic indexing (no local-mem spill)
#define SEL8(arr, idx, out) do {                                   \
    float _s0 = ((idx) & 1) ? (arr)[1] : (arr)[0];                 \
    float _s1 = ((idx) & 1) ? (arr)[3] : (arr)[2];                 \
    float _s2 = ((idx) & 1) ? (arr)[5] : (arr)[4];                 \
    float _s3 = ((idx) & 1) ? (arr)[7] : (arr)[6];                 \
    float _t0 = ((idx) & 2) ? _s1 : _s0;                           \
    float _t1 = ((idx) & 2) ? _s3 : _s2;                           \
    (out) = ((idx) & 4) ? _t1 : _t0;                               \
} while (0)

// ============ K1: Q/K/V projections (16 rows/block, 2x4 tile) ============
__global__ __launch_bounds__(256) void k1_qkv(const float* __restrict__ hem,
                                              const float* __restrict__ Wq,
                                              const float* __restrict__ Wk,
                                              const float* __restrict__ Wv) {
    __shared__ __align__(16) float ws[64 * 128];
    __shared__ float xs[16 * 128];
    int b = blockIdx.y, n0 = blockIdx.x * 16, t = threadIdx.x;
    for (int e = t; e < 2048; e += 256)
        xs[e] = hem[((size_t)b * NN + n0) * DD + e];
    int rg = t >> 5, c4 = (t & 31) * 4;
    for (int wi = 0; wi < 3; wi++) {
        const float* W = (wi == 0) ? Wq : (wi == 1) ? Wk : Wv;
        float* O = (wi == 0) ? g_Q : (wi == 1) ? g_K : g_V;
        float acc[2][4] = {};
        for (int dc = 0; dc < 2; dc++) {
            __syncthreads();
            for (int e = t; e < 8192; e += 256) {
                int h = e >> 10, rem = e & 1023, dl = rem >> 4, k = rem & 15;
                ws[dl * 128 + h * 16 + k] = W[h * 2048 + (dc * 64 + dl) * 16 + k];
            }
            __syncthreads();
#pragma unroll 8
            for (int dl = 0; dl < 64; dl++) {
                int d = dc * 64 + dl;
                float4 w = *(const float4*)&ws[dl * 128 + c4];
                float x0v = xs[rg * 128 + d], x1v = xs[(rg + 8) * 128 + d];
                acc[0][0] += x0v * w.x; acc[0][1] += x0v * w.y;
                acc[0][2] += x0v * w.z; acc[0][3] += x0v * w.w;
                acc[1][0] += x1v * w.x; acc[1][1] += x1v * w.y;
                acc[1][2] += x1v * w.z; acc[1][3] += x1v * w.w;
            }
        }
#pragma unroll
        for (int r = 0; r < 2; r++)
            *(float4*)&O[((size_t)b * NN + n0 + rg + r * 8) * DD + c4] =
                make_float4(acc[r][0], acc[r][1], acc[r][2], acc[r][3]);
    }
}

// ==== K2 (flash): scores + score_aggr MLP + online softmax + P@V -> heads ====
// block = (8 n-rows of one b), 8 warps (1 row/warp), lane <-> m within 32-chunk.
__global__ __launch_bounds__(256) void k2_flash(const float* __restrict__ route,
                                                const float* __restrict__ sw1,
                                                const float* __restrict__ sb1,
                                                const float* __restrict__ sw2,
                                                const float* __restrict__ sb2) {
    __shared__ __align__(16) float Qs[8 * 128];   // 4096 B
    __shared__ __align__(16) float Ks[32 * 132];  // 16896 B (pad 132: conflict-free LDS.128)
    __shared__ __align__(16) float Vs[32 * 128];  // 16384 B
    __shared__ float ps[8 * 8 * 33];              // 8448 B  probs [warp][h][m], 33-stride
    __shared__ __align__(16) float w1s[256];
    __shared__ __align__(16) float w2s[128];
    __shared__ float b1s[16], b2s[8];

    int b = blockIdx.y, n0 = blockIdx.x * 8, t = threadIdx.x;
    int w = t >> 5, lane = t & 31;
    int n = n0 + w;
    int hme = lane >> 2;                          // head owned for PV (4 lanes/head)

    if (t < 256) {
        // Qs: 8 rows * 128 floats = 256 float4 slots
        int m = t >> 5, d4 = (t & 31) * 4;
        *(float4*)&Qs[m * 128 + d4] =
            *(const float4*)&g_Q[((size_t)b * NN + n0 + m) * DD + d4];
    }
    w1s[t] = sw1[t];
    if (t < 128) w2s[t] = sw2[t];
    if (t < 16) b1s[t] = sb1[t];
    if (t < 8) b2s[t] = sb2[t];

    float M[8], L[8];
#pragma unroll
    for (int h = 0; h < 8; h++) { M[h] = -1e30f; L[h] = 0.f; }
    float acc0 = 0.f, acc1 = 0.f, acc2 = 0.f, acc3 = 0.f;

#pragma unroll 1
    for (int mc = 0; mc < 8; mc++) {
        __syncthreads();
        // stage K,V chunk: rows m = mc*32 .. +31, 128 floats each
#pragma unroll
        for (int i = 0; i < 4; i++) {
            int e = t + i * 256;                  // 0..1023 float4 slots
            int m = e >> 5, d4 = (e & 31) * 4;
            size_t gb = ((size_t)b * NN + mc * 32 + m) * DD + d4;
            *(float4*)&Ks[m * 132 + d4] = *(const float4*)&g_K[gb];
            *(float4*)&Vs[m * 128 + d4] = *(const float4*)&g_V[gb];
        }
        __syncthreads();

        // ---- scores s[h] for position (n, m = mc*32+lane) ----
        float s[8];
#pragma unroll
        for (int h = 0; h < 8; h++) {
            float4 k0 = *(const float4*)&Ks[lane * 132 + h * 16];
            float4 k1 = *(const float4*)&Ks[lane * 132 + h * 16 + 4];
            float4 k2 = *(const float4*)&Ks[lane * 132 + h * 16 + 8];
            float4 k3 = *(const float4*)&Ks[lane * 132 + h * 16 + 12];
            float4 q0 = *(const float4*)&Qs[w * 128 + h * 16];
            float4 q1 = *(const float4*)&Qs[w * 128 + h * 16 + 4];
            float4 q2 = *(const float4*)&Qs[w * 128 + h * 16 + 8];
            float4 q3 = *(const float4*)&Qs[w * 128 + h * 16 + 12];
            s[h] = q0.x * k0.x + q0.y * k0.y + q0.z * k0.z + q0.w * k0.w
                 + q1.x * k1.x + q1.y * k1.y + q1.z * k1.z + q1.w * k1.w
                 + q2.x * k2.x + q2.y * k2.y + q2.z * k2.z + q2.w * k2.w
                 + q3.x * k3.x + q3.y * k3.y + q3.z * k3.z + q3.w * k3.w;
        }
        // ---- route (coalesced over lanes) ----
        float r[8];
#pragma unroll
        for (int h = 0; h < 8; h++)
            r[h] = route[(((size_t)h * BB + b) * NN + n) * NN + mc * 32 + lane];

        // ---- score_aggr MLP: 16 -> relu16 -> 8 ----
        float hd[16];
#pragma unroll
        for (int j = 0; j < 16; j++) hd[j] = b1s[j];
#pragma unroll
        for (int i = 0; i < 16; i++) {
            float xi = (i < 8) ? s[i] : r[i - 8];
            float4 wa = *(const float4*)&w1s[i * 16];
            float4 wb = *(const float4*)&w1s[i * 16 + 4];
            float4 wc = *(const float4*)&w1s[i * 16 + 8];
            float4 wd = *(const float4*)&w1s[i * 16 + 12];
            hd[0] += xi * wa.x; hd[1] += xi * wa.y; hd[2] += xi * wa.z; hd[3] += xi * wa.w;
            hd[4] += xi * wb.x; hd[5] += xi * wb.y; hd[6] += xi * wb.z; hd[7] += xi * wb.w;
            hd[8] += xi * wc.x; hd[9] += xi * wc.y; hd[10] += xi * wc.z; hd[11] += xi * wc.w;
            hd[12] += xi * wd.x; hd[13] += xi * wd.y; hd[14] += xi * wd.z; hd[15] += xi * wd.w;
        }
        float a[8];
#pragma unroll
        for (int h = 0; h < 8; h++) a[h] = b2s[h];
#pragma unroll
        for (int j = 0; j < 16; j++) {
            float hj = fmaxf(hd[j], 0.f);
            float4 wa = *(const float4*)&w2s[j * 8];
            float4 wb = *(const float4*)&w2s[j * 8 + 4];
            a[0] += hj * wa.x; a[1] += hj * wa.y; a[2] += hj * wa.z; a[3] += hj * wa.w;
            a[4] += hj * wb.x; a[5] += hj * wb.y; a[6] += hj * wb.z; a[7] += hj * wb.w;
        }

        // ---- online softmax update + stash probs ----
        float sc[8];
#pragma unroll
        for (int h = 0; h < 8; h++) {
            float cm = a[h];
#pragma unroll
            for (int o = 16; o > 0; o >>= 1)
                cm = fmaxf(cm, __shfl_xor_sync(0xffffffffu, cm, o));
            float nm = fmaxf(M[h], cm);
            float ev = __expf(a[h] - nm);
            float cs = ev;
#pragma unroll
            for (int o = 16; o > 0; o >>= 1)
                cs += __shfl_xor_sync(0xffffffffu, cs, o);
            sc[h] = __expf(M[h] - nm);
            L[h] = L[h] * sc[h] + cs;
            M[h] = nm;
            ps[(w * 8 + h) * 33 + lane] = ev;
        }
        float sown;
        SEL8(sc, hme, sown);
        acc0 *= sown; acc1 *= sown; acc2 *= sown; acc3 *= sown;
        __syncwarp();

        // ---- P @ V accumulate (lane owns d = lane*4 .. +3, within head hme) ----
#pragma unroll
        for (int m = 0; m < 32; m++) {
            float p = ps[(w * 8 + hme) * 33 + m];
            float4 v = *(const float4*)&Vs[m * 128 + lane * 4];
            acc0 += p * v.x; acc1 += p * v.y; acc2 += p * v.z; acc3 += p * v.w;
        }
        __syncwarp();
    }
    float Lown;
    SEL8(L, hme, Lown);
    float inv = 1.f / Lown;
    *(float4*)&g_heads[((size_t)b * NN + n) * DD + lane * 4] =
        make_float4(acc0 * inv, acc1 * inv, acc2 * inv, acc3 * inv);
}

// ============ K4: heads @ W_out + h_em -> x0, LN partials[0] ============
__global__ __launch_bounds__(256) void k4_out(const float* __restrict__ Wo,
                                              const float* __restrict__ hem) {
    __shared__ __align__(16) float ws[64 * 128];
    __shared__ float hs[16 * 128];
    __shared__ float red[16];
    int b = blockIdx.y, n0 = blockIdx.x * 16, t = threadIdx.x;
    int warp = t >> 5, lane = t & 31;
    for (int e = t; e < 2048; e += 256)
        hs[e] = g_heads[((size_t)b * NN + n0) * DD + e];
    int rg = warp, c4 = lane * 4;
    float acc[2][4] = {};
    for (int jc = 0; jc < 2; jc++) {
        __syncthreads();
        for (int e = t; e < 8192; e += 256) ws[e] = Wo[jc * 8192 + e];
        __syncthreads();
#pragma unroll 8
        for (int jl = 0; jl < 64; jl++) {
            float4 w = *(const float4*)&ws[jl * 128 + c4];
            float h0 = hs[rg * 128 + jc * 64 + jl], h1 = hs[(rg + 8) * 128 + jc * 64 + jl];
            acc[0][0] += h0 * w.x; acc[0][1] += h0 * w.y;
            acc[0][2] += h0 * w.z; acc[0][3] += h0 * w.w;
            acc[1][0] += h1 * w.x; acc[1][1] += h1 * w.y;
            acc[1][2] += h1 * w.z; acc[1][3] += h1 * w.w;
        }
    }
    float ls = 0.f, lq = 0.f;
#pragma unroll
    for (int r = 0; r < 2; r++) {
        size_t base = ((size_t)b * NN + n0 + rg + r * 8) * DD + c4;
        float4 he = *(const float4*)&hem[base];
        float v0 = acc[r][0] + he.x, v1 = acc[r][1] + he.y;
        float v2 = acc[r][2] + he.z, v3 = acc[r][3] + he.w;
        *(float4*)&g_x0[base] = make_float4(v0, v1, v2, v3);
        ls += v0 + v1 + v2 + v3;
        lq += v0 * v0 + v1 * v1 + v2 * v2 + v3 * v3;
    }
#pragma unroll
    for (int o = 16; o > 0; o >>= 1) {
        ls += __shfl_xor_sync(0xffffffffu, ls, o);
        lq += __shfl_xor_sync(0xffffffffu, lq, o);
    }
    if (lane == 0) { red[warp] = ls; red[8 + warp] = lq; }
    __syncthreads();
    if (t == 0) {
        float s = 0.f, q = 0.f;
        for (int w = 0; w < 8; w++) { s += red[w]; q += red[8 + w]; }
        g_ps[0][b * 16 + blockIdx.x] = s;
        g_pq[0][b * 16 + blockIdx.x] = q;
    }
}

// ============ finalize LN stats (ddof=1) ============
__global__ void k_fin(int which) {
    int b = threadIdx.x;
    if (b < BB) {
        double s = 0.0, q = 0.0;
        for (int i = 0; i < 16; i++) {
            s += (double)g_ps[which][b * 16 + i];
            q += (double)g_pq[which][b * 16 + i];
        }
        double n = (double)(NN * DD);
        double mean = s / n;
        double var = (q - s * s / n) / (n - 1.0);
        g_mu[which][b] = (float)mean;
        g_iv[which][b] = (float)(1.0 / sqrt(var + EPSV));
    }
}

// ============ K6: x = LN(x0); hdn = relu(x @ ff_w1) ============
__global__ __launch_bounds__(256) void k6_ff1(const float* __restrict__ w1) {
    __shared__ __align__(16) float ws[64 * 128];
    __shared__ float xs[16 * 128];
    int b = blockIdx.y, n0 = blockIdx.x * 16, t = threadIdx.x;
    float mu = g_mu[0][b], iv = g_iv[0][b];
    for (int e = t; e < 2048; e += 256)
        xs[e] = (g_x0[((size_t)b * NN + n0) * DD + e] - mu) * iv;
    int rg = t >> 5, f4 = (t & 31) * 4;
    for (int ft = 0; ft < 4; ft++) {
        float acc[2][4] = {};
        for (int dc = 0; dc < 2; dc++) {
            __syncthreads();
            for (int e = t; e < 8192; e += 256)
                ws[e] = w1[(dc * 64 + (e >> 7)) * FF + ft * 128 + (e & 127)];
            __syncthreads();
#pragma unroll 8
            for (int dl = 0; dl < 64; dl++) {
                int d = dc * 64 + dl;
                float4 w = *(const float4*)&ws[dl * 128 + f4];
                float x0v = xs[rg * 128 + d], x1v = xs[(rg + 8) * 128 + d];
                acc[0][0] += x0v * w.x; acc[0][1] += x0v * w.y;
                acc[0][2] += x0v * w.z; acc[0][3] += x0v * w.w;
                acc[1][0] += x1v * w.x; acc[1][1] += x1v * w.y;
                acc[1][2] += x1v * w.z; acc[1][3] += x1v * w.w;
            }
        }
#pragma unroll
        for (int r = 0; r < 2; r++)
            *(float4*)&g_hdn[((size_t)b * NN + n0 + rg + r * 8) * FF + ft * 128 + f4] =
                make_float4(fmaxf(acc[r][0], 0.f), fmaxf(acc[r][1], 0.f),
                            fmaxf(acc[r][2], 0.f), fmaxf(acc[r][3], 0.f));
    }
}

// ============ K7: y0 = hdn @ ff_w2 + x, LN partials[1] ============
__global__ __launch_bounds__(256) void k7_ff2(const float* __restrict__ w2) {
    __shared__ __align__(16) float ws[64 * 128];
    __shared__ float hsm[16 * 64];
    __shared__ float red[16];
    int b = blockIdx.y, n0 = blockIdx.x * 16, t = threadIdx.x;
    int warp = t >> 5, lane = t & 31;
    int rg = warp, d4 = lane * 4;
    float acc[2][4] = {};
    for (int kc = 0; kc < 8; kc++) {
        __syncthreads();
        for (int e = t; e < 8192; e += 256) ws[e] = w2[kc * 8192 + e];
        for (int e = t; e < 1024; e += 256)
            hsm[e] = g_hdn[((size_t)b * NN + n0 + (e >> 6)) * FF + kc * 64 + (e & 63)];
        __syncthreads();
#pragma unroll 8
        for (int kl = 0; kl < 64; kl++) {
            float4 w = *(const float4*)&ws[kl * 128 + d4];
            float h0 = hsm[rg * 64 + kl], h1 = hsm[(rg + 8) * 64 + kl];
            acc[0][0] += h0 * w.x; acc[0][1] += h0 * w.y;
            acc[0][2] += h0 * w.z; acc[0][3] += h0 * w.w;
            acc[1][0] += h1 * w.x; acc[1][1] += h1 * w.y;
            acc[1][2] += h1 * w.z; acc[1][3] += h1 * w.w;
        }
    }
    float mu = g_mu[0][b], iv = g_iv[0][b];
    float ls = 0.f, lq = 0.f;
#pragma unroll
    for (int r = 0; r < 2; r++) {
        size_t base = ((size_t)b * NN + n0 + rg + r * 8) * DD + d4;
        float4 xv = *(const float4*)&g_x0[base];
        float v0 = acc[r][0] + (xv.x - mu) * iv;
        float v1 = acc[r][1] + (xv.y - mu) * iv;
        float v2 = acc[r][2] + (xv.z - mu) * iv;
        float v3 = acc[r][3] + (xv.w - mu) * iv;
        *(float4*)&g_y0[base] = make_float4(v0, v1, v2, v3);
        ls += v0 + v1 + v2 + v3;
        lq += v0 * v0 + v1 * v1 + v2 * v2 + v3 * v3;
    }
#pragma unroll
    for (int o = 16; o > 0; o >>= 1) {
        ls += __shfl_xor_sync(0xffffffffu, ls, o);
        lq += __shfl_xor_sync(0xffffffffu, lq, o);
    }
    if (lane == 0) { red[warp] = ls; red[8 + warp] = lq; }
    __syncthreads();
    if (t == 0) {
        float s = 0.f, q = 0.f;
        for (int w = 0; w < 8; w++) { s += red[w]; q += red[8 + w]; }
        g_ps[1][b * 16 + blockIdx.x] = s;
        g_pq[1][b * 16 + blockIdx.x] = q;
    }
}

// ============ K8: out1 = LN(y0) ============
__global__ __launch_bounds__(256) void k8_norm(float* __restrict__ out) {
    int i = blockIdx.x * 256 + threadIdx.x;   // 524288 float4
    int b = i >> 13;
    float mu = g_mu[1][b], iv = g_iv[1][b];
    float4 v = ((const float4*)g_y0)[i];
    v.x = (v.x - mu) * iv; v.y = (v.y - mu) * iv;
    v.z = (v.z - mu) * iv; v.w = (v.w - mu) * iv;
    ((float4*)out)[i] = v;
}

// ============ launcher ============
extern "C" void kernel_launch(void* const* d_in, const int* in_sizes, int n_in,
                              void* d_out, int out_size) {
    const float* hem = (const float*)d_in[0];
    const float* route = (const float*)d_in[1];
    const float* Wq = (const float*)d_in[2];
    const float* Wk = (const float*)d_in[3];
    const float* Wv = (const float*)d_in[4];
    const float* Wo = (const float*)d_in[5];
    const float* sw1 = (const float*)d_in[6];
    const float* sb1 = (const float*)d_in[7];
    const float* sw2 = (const float*)d_in[8];
    const float* sb2 = (const float*)d_in[9];
    const float* fw1 = (const float*)d_in[10];
    const float* fw2 = (const float*)d_in[11];
    float* out = (float*)d_out;

    const long long OUT1 = (long long)BB * NN * DD;        // 2097152
    const long long ROUTE = (long long)HH * BB * NN * NN;  // 33554432

    dim3 g16(16, BB);
    dim3 g32(32, BB);

    k1_qkv<<<g16, 256>>>(hem, Wq, Wk, Wv);
    k2_flash<<<g32, 256>>>(route, sw1, sb1, sw2, sb2);
    k4_out<<<g16, 256>>>(Wo, hem);
    k_fin<<<1, 64>>>(0);
    k6_ff1<<<g16, 256>>>(fw1);
    k7_ff2<<<g16, 256>>>(fw2);
    k_fin<<<1, 64>>>(1);
    k8_norm<<<2048, 256>>>(out);

    if ((long long)out_size >= OUT1 + ROUTE) {
        cudaMemcpyAsync(out + OUT1, route, (size_t)ROUTE * sizeof(float),
                        cudaMemcpyDeviceToDevice);
    }
}

// round 12
// speedup vs baseline: 3.6992x; 1.6369x over previous
#include <cuda_runtime.h>
#include <math.h>

#define BB 64
#define NN 256
#define DD 128
#define HH 8
#define FF 512
#define EPSV 1e-5

// ------- scratch (device globals; no allocations anywhere) -------
__device__ float g_Q[BB * NN * DD];
__device__ float g_K[BB * NN * DD];
__device__ float g_V[BB * NN * DD];
__device__ float g_heads[BB * NN * DD];
__device__ float g_x0[BB * NN * DD];
__device__ float g_hdn[BB * NN * FF];
__device__ float g_y0[BB * NN * DD];
__device__ float g_ps[2][BB * 16];
__device__ float g_pq[2][BB * 16];

// select arr[idx] for idx in 0..7 without dynamic indexing (no local-mem spill)
#define SEL8(arr, idx, out) do {                                   \
    float _s0 = ((idx) & 1) ? (arr)[1] : (arr)[0];                 \
    float _s1 = ((idx) & 1) ? (arr)[3] : (arr)[2];                 \
    float _s2 = ((idx) & 1) ? (arr)[5] : (arr)[4];                 \
    float _s3 = ((idx) & 1) ? (arr)[7] : (arr)[6];                 \
    float _t0 = ((idx) & 2) ? _s1 : _s0;                           \
    float _t1 = ((idx) & 2) ? _s3 : _s2;                           \
    (out) = ((idx) & 4) ? _t1 : _t0;                               \
} while (0)

// finalize LN stats for batch b from 16 partials (ddof=1), double precision
__device__ __forceinline__ void ln_finalize(int which, int b, float* mu, float* iv) {
    double s = 0.0, q = 0.0;
#pragma unroll
    for (int i = 0; i < 16; i++) {
        s += (double)g_ps[which][b * 16 + i];
        q += (double)g_pq[which][b * 16 + i];
    }
    double n = (double)(NN * DD);
    double mean = s / n;
    double var = (q - s * s / n) / (n - 1.0);
    *mu = (float)mean;
    *iv = (float)(1.0 / sqrt(var + EPSV));
}

// ============ K1: Q/K/V projections (16 rows/block, 2x4 tile) ============
__global__ __launch_bounds__(256) void k1_qkv(const float* __restrict__ hem,
                                              const float* __restrict__ Wq,
                                              const float* __restrict__ Wk,
                                              const float* __restrict__ Wv) {
    __shared__ __align__(16) float ws[64 * 128];
    __shared__ __align__(16) float xs[16 * 128];
    int b = blockIdx.y, n0 = blockIdx.x * 16, t = threadIdx.x;
    const float4* hem4 = (const float4*)(hem + ((size_t)b * NN + n0) * DD);
    for (int e = t; e < 512; e += 256)
        ((float4*)xs)[e] = hem4[e];
    int rg = t >> 5, c4 = (t & 31) * 4;
    for (int wi = 0; wi < 3; wi++) {
        const float* W = (wi == 0) ? Wq : (wi == 1) ? Wk : Wv;
        const float4* W4 = (const float4*)W;
        float* O = (wi == 0) ? g_Q : (wi == 1) ? g_K : g_V;
        float acc[2][4] = {};
        for (int dc = 0; dc < 2; dc++) {
            __syncthreads();
            // transpose-stage W[h][d][k] -> ws[dl*128 + h*16 + k], float4 granularity
            for (int e = t; e < 2048; e += 256) {
                int h = e >> 8, dl = (e >> 2) & 63, k4 = e & 3;
                ((float4*)ws)[dl * 32 + h * 4 + k4] =
                    W4[h * 512 + (dc * 64 + dl) * 4 + k4];
            }
            __syncthreads();
#pragma unroll 8
            for (int dl = 0; dl < 64; dl++) {
                int d = dc * 64 + dl;
                float4 w = *(const float4*)&ws[dl * 128 + c4];
                float x0v = xs[rg * 128 + d], x1v = xs[(rg + 8) * 128 + d];
                acc[0][0] += x0v * w.x; acc[0][1] += x0v * w.y;
                acc[0][2] += x0v * w.z; acc[0][3] += x0v * w.w;
                acc[1][0] += x1v * w.x; acc[1][1] += x1v * w.y;
                acc[1][2] += x1v * w.z; acc[1][3] += x1v * w.w;
            }
        }
#pragma unroll
        for (int r = 0; r < 2; r++)
            *(float4*)&O[((size_t)b * NN + n0 + rg + r * 8) * DD + c4] =
                make_float4(acc[r][0], acc[r][1], acc[r][2], acc[r][3]);
    }
}

// ==== K2 (flash): scores + score_aggr MLP + online softmax + P@V -> heads ====
// Also passes route through to the output tail (read once -> store once).
__global__ __launch_bounds__(256) void k2_flash(const float* __restrict__ route,
                                                const float* __restrict__ sw1,
                                                const float* __restrict__ sb1,
                                                const float* __restrict__ sw2,
                                                const float* __restrict__ sb2,
                                                float* __restrict__ rout) {
    __shared__ __align__(16) float Qs[8 * 128];   // 4096 B
    __shared__ __align__(16) float Ks[32 * 132];  // 16896 B (pad 132: conflict-free LDS.128)
    __shared__ __align__(16) float Vs[32 * 128];  // 16384 B
    __shared__ float ps[8 * 8 * 33];              // 8448 B  probs [warp][h][m], 33-stride
    __shared__ __align__(16) float w1s[256];
    __shared__ __align__(16) float w2s[128];
    __shared__ float b1s[16], b2s[8];

    int b = blockIdx.y, n0 = blockIdx.x * 8, t = threadIdx.x;
    int w = t >> 5, lane = t & 31;
    int n = n0 + w;
    int hme = lane >> 2;                          // head owned for PV (4 lanes/head)

    {   // Qs: 8 rows * 128 floats = 256 float4 slots
        int m = t >> 5, d4 = (t & 31) * 4;
        *(float4*)&Qs[m * 128 + d4] =
            *(const float4*)&g_Q[((size_t)b * NN + n0 + m) * DD + d4];
    }
    w1s[t] = sw1[t];
    if (t < 128) w2s[t] = sw2[t];
    if (t < 16) b1s[t] = sb1[t];
    if (t < 8) b2s[t] = sb2[t];

    float M[8], L[8];
#pragma unroll
    for (int h = 0; h < 8; h++) { M[h] = -1e30f; L[h] = 0.f; }
    float acc0 = 0.f, acc1 = 0.f, acc2 = 0.f, acc3 = 0.f;

#pragma unroll 1
    for (int mc = 0; mc < 8; mc++) {
        __syncthreads();
        // stage K,V chunk: rows m = mc*32 .. +31, 128 floats each
#pragma unroll
        for (int i = 0; i < 4; i++) {
            int e = t + i * 256;                  // 0..1023 float4 slots
            int m = e >> 5, d4 = (e & 31) * 4;
            size_t gb = ((size_t)b * NN + mc * 32 + m) * DD + d4;
            *(float4*)&Ks[m * 132 + d4] = *(const float4*)&g_K[gb];
            *(float4*)&Vs[m * 128 + d4] = *(const float4*)&g_V[gb];
        }
        __syncthreads();

        // ---- scores s[h] for position (n, m = mc*32+lane) ----
        float s[8];
#pragma unroll
        for (int h = 0; h < 8; h++) {
            float4 k0 = *(const float4*)&Ks[lane * 132 + h * 16];
            float4 k1 = *(const float4*)&Ks[lane * 132 + h * 16 + 4];
            float4 k2 = *(const float4*)&Ks[lane * 132 + h * 16 + 8];
            float4 k3 = *(const float4*)&Ks[lane * 132 + h * 16 + 12];
            float4 q0 = *(const float4*)&Qs[w * 128 + h * 16];
            float4 q1 = *(const float4*)&Qs[w * 128 + h * 16 + 4];
            float4 q2 = *(const float4*)&Qs[w * 128 + h * 16 + 8];
            float4 q3 = *(const float4*)&Qs[w * 128 + h * 16 + 12];
            s[h] = q0.x * k0.x + q0.y * k0.y + q0.z * k0.z + q0.w * k0.w
                 + q1.x * k1.x + q1.y * k1.y + q1.z * k1.z + q1.w * k1.w
                 + q2.x * k2.x + q2.y * k2.y + q2.z * k2.z + q2.w * k2.w
                 + q3.x * k3.x + q3.y * k3.y + q3.z * k3.z + q3.w * k3.w;
        }
        // ---- route (coalesced over lanes); pass through to output tail ----
        float r[8];
#pragma unroll
        for (int h = 0; h < 8; h++) {
            size_t ri = (((size_t)h * BB + b) * NN + n) * NN + mc * 32 + lane;
            r[h] = route[ri];
            if (rout) rout[ri] = r[h];
        }

        // ---- score_aggr MLP: 16 -> relu16 -> 8 ----
        float hd[16];
#pragma unroll
        for (int j = 0; j < 16; j++) hd[j] = b1s[j];
#pragma unroll
        for (int i = 0; i < 16; i++) {
            float xi = (i < 8) ? s[i] : r[i - 8];
            float4 wa = *(const float4*)&w1s[i * 16];
            float4 wb = *(const float4*)&w1s[i * 16 + 4];
            float4 wc = *(const float4*)&w1s[i * 16 + 8];
            float4 wd = *(const float4*)&w1s[i * 16 + 12];
            hd[0] += xi * wa.x; hd[1] += xi * wa.y; hd[2] += xi * wa.z; hd[3] += xi * wa.w;
            hd[4] += xi * wb.x; hd[5] += xi * wb.y; hd[6] += xi * wb.z; hd[7] += xi * wb.w;
            hd[8] += xi * wc.x; hd[9] += xi * wc.y; hd[10] += xi * wc.z; hd[11] += xi * wc.w;
            hd[12] += xi * wd.x; hd[13] += xi * wd.y; hd[14] += xi * wd.z; hd[15] += xi * wd.w;
        }
        float a[8];
#pragma unroll
        for (int h = 0; h < 8; h++) a[h] = b2s[h];
#pragma unroll
        for (int j = 0; j < 16; j++) {
            float hj = fmaxf(hd[j], 0.f);
            float4 wa = *(const float4*)&w2s[j * 8];
            float4 wb = *(const float4*)&w2s[j * 8 + 4];
            a[0] += hj * wa.x; a[1] += hj * wa.y; a[2] += hj * wa.z; a[3] += hj * wa.w;
            a[4] += hj * wb.x; a[5] += hj * wb.y; a[6] += hj * wb.z; a[7] += hj * wb.w;
        }

        // ---- online softmax: PIPELINED butterflies (8 independent chains) ----
        float cm[8];
#pragma unroll
        for (int h = 0; h < 8; h++) cm[h] = a[h];
#pragma unroll
        for (int o = 16; o > 0; o >>= 1)
#pragma unroll
            for (int h = 0; h < 8; h++)
                cm[h] = fmaxf(cm[h], __shfl_xor_sync(0xffffffffu, cm[h], o));
        float cs[8], sc[8];
#pragma unroll
        for (int h = 0; h < 8; h++) {
            float nm = fmaxf(M[h], cm[h]);
            float ev = __expf(a[h] - nm);
            ps[(w * 8 + h) * 33 + lane] = ev;
            cs[h] = ev;
            sc[h] = __expf(M[h] - nm);
            M[h] = nm;
        }
#pragma unroll
        for (int o = 16; o > 0; o >>= 1)
#pragma unroll
            for (int h = 0; h < 8; h++)
                cs[h] += __shfl_xor_sync(0xffffffffu, cs[h], o);
#pragma unroll
        for (int h = 0; h < 8; h++)
            L[h] = L[h] * sc[h] + cs[h];

        float sown;
        SEL8(sc, hme, sown);
        acc0 *= sown; acc1 *= sown; acc2 *= sown; acc3 *= sown;
        __syncwarp();

        // ---- P @ V accumulate (lane owns d = lane*4 .. +3, within head hme) ----
#pragma unroll
        for (int m = 0; m < 32; m++) {
            float p = ps[(w * 8 + hme) * 33 + m];
            float4 v = *(const float4*)&Vs[m * 128 + lane * 4];
            acc0 += p * v.x; acc1 += p * v.y; acc2 += p * v.z; acc3 += p * v.w;
        }
        __syncwarp();
    }
    float Lown;
    SEL8(L, hme, Lown);
    float inv = 1.f / Lown;
    *(float4*)&g_heads[((size_t)b * NN + n) * DD + lane * 4] =
        make_float4(acc0 * inv, acc1 * inv, acc2 * inv, acc3 * inv);
}

// ============ K4: heads @ W_out + h_em -> x0, LN partials[0] ============
__global__ __launch_bounds__(256) void k4_out(const float* __restrict__ Wo,
                                              const float* __restrict__ hem) {
    __shared__ __align__(16) float ws[64 * 128];
    __shared__ __align__(16) float hs[16 * 128];
    __shared__ float red[16];
    int b = blockIdx.y, n0 = blockIdx.x * 16, t = threadIdx.x;
    int warp = t >> 5, lane = t & 31;
    const float4* hd4 = (const float4*)(g_heads + ((size_t)b * NN + n0) * DD);
    for (int e = t; e < 512; e += 256)
        ((float4*)hs)[e] = hd4[e];
    int rg = warp, c4 = lane * 4;
    float acc[2][4] = {};
    const float4* Wo4 = (const float4*)Wo;
    for (int jc = 0; jc < 2; jc++) {
        __syncthreads();
        for (int e = t; e < 2048; e += 256)
            ((float4*)ws)[e] = Wo4[jc * 2048 + e];
        __syncthreads();
#pragma unroll 8
        for (int jl = 0; jl < 64; jl++) {
            float4 w = *(const float4*)&ws[jl * 128 + c4];
            float h0 = hs[rg * 128 + jc * 64 + jl], h1 = hs[(rg + 8) * 128 + jc * 64 + jl];
            acc[0][0] += h0 * w.x; acc[0][1] += h0 * w.y;
            acc[0][2] += h0 * w.z; acc[0][3] += h0 * w.w;
            acc[1][0] += h1 * w.x; acc[1][1] += h1 * w.y;
            acc[1][2] += h1 * w.z; acc[1][3] += h1 * w.w;
        }
    }
    float ls = 0.f, lq = 0.f;
#pragma unroll
    for (int r = 0; r < 2; r++) {
        size_t base = ((size_t)b * NN + n0 + rg + r * 8) * DD + c4;
        float4 he = *(const float4*)&hem[base];
        float v0 = acc[r][0] + he.x, v1 = acc[r][1] + he.y;
        float v2 = acc[r][2] + he.z, v3 = acc[r][3] + he.w;
        *(float4*)&g_x0[base] = make_float4(v0, v1, v2, v3);
        ls += v0 + v1 + v2 + v3;
        lq += v0 * v0 + v1 * v1 + v2 * v2 + v3 * v3;
    }
#pragma unroll
    for (int o = 16; o > 0; o >>= 1) {
        ls += __shfl_xor_sync(0xffffffffu, ls, o);
        lq += __shfl_xor_sync(0xffffffffu, lq, o);
    }
    if (lane == 0) { red[warp] = ls; red[8 + warp] = lq; }
    __syncthreads();
    if (t == 0) {
        float s = 0.f, q = 0.f;
        for (int w = 0; w < 8; w++) { s += red[w]; q += red[8 + w]; }
        g_ps[0][b * 16 + blockIdx.x] = s;
        g_pq[0][b * 16 + blockIdx.x] = q;
    }
}

// ============ K6: x = LN(x0); hdn = relu(x @ ff_w1) ============
__global__ __launch_bounds__(256) void k6_ff1(const float* __restrict__ w1) {
    __shared__ __align__(16) float ws[64 * 128];
    __shared__ __align__(16) float xs[16 * 128];
    __shared__ float s_mu, s_iv;
    int b = blockIdx.y, n0 = blockIdx.x * 16, t = threadIdx.x;
    if (t == 0) ln_finalize(0, b, (float*)&s_mu, (float*)&s_iv);
    __syncthreads();
    float mu = s_mu, iv = s_iv;
    const float4* x04 = (const float4*)(g_x0 + ((size_t)b * NN + n0) * DD);
    for (int e = t; e < 512; e += 256) {
        float4 v = x04[e];
        v.x = (v.x - mu) * iv; v.y = (v.y - mu) * iv;
        v.z = (v.z - mu) * iv; v.w = (v.w - mu) * iv;
        ((float4*)xs)[e] = v;
    }
    int rg = t >> 5, f4 = (t & 31) * 4;
    const float4* w14 = (const float4*)w1;
    for (int ft = 0; ft < 4; ft++) {
        float acc[2][4] = {};
        for (int dc = 0; dc < 2; dc++) {
            __syncthreads();
            for (int e = t; e < 2048; e += 256) {
                int row = e >> 5, c = e & 31;
                ((float4*)ws)[e] = w14[(dc * 64 + row) * 128 + ft * 32 + c];
            }
            __syncthreads();
#pragma unroll 8
            for (int dl = 0; dl < 64; dl++) {
                int d = dc * 64 + dl;
                float4 w = *(const float4*)&ws[dl * 128 + f4];
                float x0v = xs[rg * 128 + d], x1v = xs[(rg + 8) * 128 + d];
                acc[0][0] += x0v * w.x; acc[0][1] += x0v * w.y;
                acc[0][2] += x0v * w.z; acc[0][3] += x0v * w.w;
                acc[1][0] += x1v * w.x; acc[1][1] += x1v * w.y;
                acc[1][2] += x1v * w.z; acc[1][3] += x1v * w.w;
            }
        }
#pragma unroll
        for (int r = 0; r < 2; r++)
            *(float4*)&g_hdn[((size_t)b * NN + n0 + rg + r * 8) * FF + ft * 128 + f4] =
                make_float4(fmaxf(acc[r][0], 0.f), fmaxf(acc[r][1], 0.f),
                            fmaxf(acc[r][2], 0.f), fmaxf(acc[r][3], 0.f));
    }
}

// ============ K7: y0 = hdn @ ff_w2 + x, LN partials[1] ============
__global__ __launch_bounds__(256) void k7_ff2(const float* __restrict__ w2) {
    __shared__ __align__(16) float ws[64 * 128];
    __shared__ __align__(16) float hsm[16 * 64];
    __shared__ float red[16];
    __shared__ float s_mu, s_iv;
    int b = blockIdx.y, n0 = blockIdx.x * 16, t = threadIdx.x;
    int warp = t >> 5, lane = t & 31;
    if (t == 0) ln_finalize(0, b, (float*)&s_mu, (float*)&s_iv);
    int rg = warp, d4 = lane * 4;
    float acc[2][4] = {};
    const float4* w24 = (const float4*)w2;
    for (int kc = 0; kc < 8; kc++) {
        __syncthreads();
        for (int e = t; e < 2048; e += 256)
            ((float4*)ws)[e] = w24[kc * 2048 + e];
        {
            int e = t;                           // 256 float4 slots, 1/thread
            int r = e >> 4, c = e & 15;
            ((float4*)hsm)[e] = *(const float4*)
                &g_hdn[((size_t)b * NN + n0 + r) * FF + kc * 64 + c * 4];
        }
        __syncthreads();
#pragma unroll 8
        for (int kl = 0; kl < 64; kl++) {
            float4 w = *(const float4*)&ws[kl * 128 + d4];
            float h0 = hsm[rg * 64 + kl], h1 = hsm[(rg + 8) * 64 + kl];
            acc[0][0] += h0 * w.x; acc[0][1] += h0 * w.y;
            acc[0][2] += h0 * w.z; acc[0][3] += h0 * w.w;
            acc[1][0] += h1 * w.x; acc[1][1] += h1 * w.y;
            acc[1][2] += h1 * w.z; acc[1][3] += h1 * w.w;
        }
    }
    float mu = s_mu, iv = s_iv;
    float ls = 0.f, lq = 0.f;
#pragma unroll
    for (int r = 0; r < 2; r++) {
        size_t base = ((size_t)b * NN + n0 + rg + r * 8) * DD + d4;
        float4 xv = *(const float4*)&g_x0[base];
        float v0 = acc[r][0] + (xv.x - mu) * iv;
        float v1 = acc[r][1] + (xv.y - mu) * iv;
        float v2 = acc[r][2] + (xv.z - mu) * iv;
        float v3 = acc[r][3] + (xv.w - mu) * iv;
        *(float4*)&g_y0[base] = make_float4(v0, v1, v2, v3);
        ls += v0 + v1 + v2 + v3;
        lq += v0 * v0 + v1 * v1 + v2 * v2 + v3 * v3;
    }
#pragma unroll
    for (int o = 16; o > 0; o >>= 1) {
        ls += __shfl_xor_sync(0xffffffffu, ls, o);
        lq += __shfl_xor_sync(0xffffffffu, lq, o);
    }
    if (lane == 0) { red[warp] = ls; red[8 + warp] = lq; }
    __syncthreads();
    if (t == 0) {
        float s = 0.f, q = 0.f;
        for (int w = 0; w < 8; w++) { s += red[w]; q += red[8 + w]; }
        g_ps[1][b * 16 + blockIdx.x] = s;
        g_pq[1][b * 16 + blockIdx.x] = q;
    }
}

// ============ K8: out1 = LN(y0) ============
__global__ __launch_bounds__(256) void k8_norm(float* __restrict__ out) {
    __shared__ float s_mu, s_iv;
    int i = blockIdx.x * 256 + threadIdx.x;   // 524288 float4; one b per block
    int b = i >> 13;
    if (threadIdx.x == 0) ln_finalize(1, b, (float*)&s_mu, (float*)&s_iv);
    __syncthreads();
    float mu = s_mu, iv = s_iv;
    float4 v = ((const float4*)g_y0)[i];
    v.x = (v.x - mu) * iv; v.y = (v.y - mu) * iv;
    v.z = (v.z - mu) * iv; v.w = (v.w - mu) * iv;
    ((float4*)out)[i] = v;
}

// ============ launcher ============
extern "C" void kernel_launch(void* const* d_in, const int* in_sizes, int n_in,
                              void* d_out, int out_size) {
    const float* hem = (const float*)d_in[0];
    const float* route = (const float*)d_in[1];
    const float* Wq = (const float*)d_in[2];
    const float* Wk = (const float*)d_in[3];
    const float* Wv = (const float*)d_in[4];
    const float* Wo = (const float*)d_in[5];
    const float* sw1 = (const float*)d_in[6];
    const float* sb1 = (const float*)d_in[7];
    const float* sw2 = (const float*)d_in[8];
    const float* sb2 = (const float*)d_in[9];
    const float* fw1 = (const float*)d_in[10];
    const float* fw2 = (const float*)d_in[11];
    float* out = (float*)d_out;

    const long long OUT1 = (long long)BB * NN * DD;        // 2097152
    const long long ROUTE = (long long)HH * BB * NN * NN;  // 33554432
    float* rout = ((long long)out_size >= OUT1 + ROUTE) ? (out + OUT1) : (float*)0;

    dim3 g16(16, BB);
    dim3 g32(32, BB);

    k1_qkv<<<g16, 256>>>(hem, Wq, Wk, Wv);
    k2_flash<<<g32, 256>>>(route, sw1, sb1, sw2, sb2, rout);
    k4_out<<<g16, 256>>>(Wo, hem);
    k6_ff1<<<g16, 256>>>(fw1);
    k7_ff2<<<g16, 256>>>(fw2);
    k8_norm<<<2048, 256>>>(out);
}

// round 13
// speedup vs baseline: 3.9739x; 1.0743x over previous
#include <cuda_runtime.h>
#include <math.h>

#define BB 64
#define NN 256
#define DD 128
#define HH 8
#define FF 512
#define EPSV 1e-5

// ------- scratch (device globals; no allocations anywhere) -------
__device__ float g_Q[BB * NN * DD];
__device__ float g_K[BB * NN * DD];
__device__ float g_V[BB * NN * DD];
__device__ float g_heads[BB * NN * DD];
__device__ float g_x0[BB * NN * DD];
__device__ float g_hdn[BB * NN * FF];
__device__ float g_y0[BB * NN * DD];
__device__ float g_ps[2][BB * 8];
__device__ float g_pq[2][BB * 8];

// select arr[idx] for idx in 0..7 without dynamic indexing (no local-mem spill)
#define SEL8(arr, idx, out) do {                                   \
    float _s0 = ((idx) & 1) ? (arr)[1] : (arr)[0];                 \
    float _s1 = ((idx) & 1) ? (arr)[3] : (arr)[2];                 \
    float _s2 = ((idx) & 1) ? (arr)[5] : (arr)[4];                 \
    float _s3 = ((idx) & 1) ? (arr)[7] : (arr)[6];                 \
    float _t0 = ((idx) & 2) ? _s1 : _s0;                           \
    float _t1 = ((idx) & 2) ? _s3 : _s2;                           \
    (out) = ((idx) & 4) ? _t1 : _t0;                               \
} while (0)

// finalize LN stats for batch b from 8 partials (ddof=1), double precision
__device__ __forceinline__ void ln_finalize(int which, int b, float* mu, float* iv) {
    double s = 0.0, q = 0.0;
#pragma unroll
    for (int i = 0; i < 8; i++) {
        s += (double)g_ps[which][b * 8 + i];
        q += (double)g_pq[which][b * 8 + i];
    }
    double n = (double)(NN * DD);
    double mean = s / n;
    double var = (q - s * s / n) / (n - 1.0);
    *mu = (float)mean;
    *iv = (float)(1.0 / sqrt(var + EPSV));
}

// GEMM micro-tile: 4 k-steps, 4 rows x 4 cols per thread.
// xv[r] = float4 broadcast of activations, wv = float4 of weights per k-step.
#define GEMM_STEP4(acc, xs_row_ptr, xs_stride, kbase, ws, lane)            \
    do {                                                                   \
        float4 _xv[4];                                                     \
        _Pragma("unroll")                                                  \
        for (int _r = 0; _r < 4; _r++)                                     \
            _xv[_r] = *(const float4*)&(xs_row_ptr)[_r * (xs_stride) + (kbase)]; \
        _Pragma("unroll")                                                  \
        for (int _j = 0; _j < 4; _j++) {                                   \
            float4 _wv = *(const float4*)&(ws)[((kbase) % 32 + _j) * 128 + (lane) * 4]; \
            _Pragma("unroll")                                              \
            for (int _r = 0; _r < 4; _r++) {                               \
                float _xj = (_j == 0) ? _xv[_r].x : (_j == 1) ? _xv[_r].y  \
                          : (_j == 2) ? _xv[_r].z : _xv[_r].w;             \
                acc[_r][0] += _xj * _wv.x; acc[_r][1] += _xj * _wv.y;      \
                acc[_r][2] += _xj * _wv.z; acc[_r][3] += _xj * _wv.w;      \
            }                                                              \
        }                                                                  \
    } while (0)

// ============ K1: Q/K/V projections (32 rows/block, 4x4 tile) ============
__global__ __launch_bounds__(256) void k1_qkv(const float* __restrict__ hem,
                                              const float* __restrict__ Wq,
                                              const float* __restrict__ Wk,
                                              const float* __restrict__ Wv) {
    __shared__ __align__(16) float ws[32 * 128];
    __shared__ __align__(16) float xs[32 * 128];
    int b = blockIdx.y, n0 = blockIdx.x * 32, t = threadIdx.x;
    int w = t >> 5, lane = t & 31;
    const float4* hem4 = (const float4*)(hem + ((size_t)b * NN + n0) * DD);
    for (int e = t; e < 1024; e += 256)
        ((float4*)xs)[e] = hem4[e];
    const float* xrow = &xs[(w * 4) * 128];

    for (int wi = 0; wi < 3; wi++) {
        const float* W = (wi == 0) ? Wq : (wi == 1) ? Wk : Wv;
        const float4* W4 = (const float4*)W;
        float* O = (wi == 0) ? g_Q : (wi == 1) ? g_K : g_V;
        float acc[4][4] = {};
        for (int dc = 0; dc < 4; dc++) {
            __syncthreads();
            // transpose-stage W[h][d][k] -> ws[dl*128 + h*16 + k]
            for (int e = t; e < 1024; e += 256) {
                int h = e >> 7, dl = (e >> 2) & 31, k4 = e & 3;
                ((float4*)ws)[dl * 32 + h * 4 + k4] =
                    W4[h * 512 + (dc * 32 + dl) * 4 + k4];
            }
            __syncthreads();
#pragma unroll 2
            for (int dl = 0; dl < 32; dl += 4) {
                float4 xv[4];
#pragma unroll
                for (int r = 0; r < 4; r++)
                    xv[r] = *(const float4*)&xrow[r * 128 + dc * 32 + dl];
#pragma unroll
                for (int j = 0; j < 4; j++) {
                    float4 wv = *(const float4*)&ws[(dl + j) * 128 + lane * 4];
#pragma unroll
                    for (int r = 0; r < 4; r++) {
                        float xj = (j == 0) ? xv[r].x : (j == 1) ? xv[r].y
                                 : (j == 2) ? xv[r].z : xv[r].w;
                        acc[r][0] += xj * wv.x; acc[r][1] += xj * wv.y;
                        acc[r][2] += xj * wv.z; acc[r][3] += xj * wv.w;
                    }
                }
            }
        }
#pragma unroll
        for (int r = 0; r < 4; r++)
            *(float4*)&O[((size_t)b * NN + n0 + w * 4 + r) * DD + lane * 4] =
                make_float4(acc[r][0], acc[r][1], acc[r][2], acc[r][3]);
    }
}

// ==== K2 (flash): scores + score_aggr MLP + online softmax + P@V -> heads ====
// Also passes route through to the output tail (read once -> store once).
__global__ __launch_bounds__(256) void k2_flash(const float* __restrict__ route,
                                                const float* __restrict__ sw1,
                                                const float* __restrict__ sb1,
                                                const float* __restrict__ sw2,
                                                const float* __restrict__ sb2,
                                                float* __restrict__ rout) {
    __shared__ __align__(16) float Qs[8 * 128];   // 4096 B
    __shared__ __align__(16) float Ks[32 * 132];  // 16896 B (pad 132: conflict-free LDS.128)
    __shared__ __align__(16) float Vs[32 * 128];  // 16384 B
    __shared__ float ps[8 * 8 * 33];              // 8448 B  probs [warp][h][m], 33-stride
    __shared__ __align__(16) float w1s[256];
    __shared__ __align__(16) float w2s[128];
    __shared__ float b1s[16], b2s[8];

    int b = blockIdx.y, n0 = blockIdx.x * 8, t = threadIdx.x;
    int w = t >> 5, lane = t & 31;
    int n = n0 + w;
    int hme = lane >> 2;                          // head owned for PV (4 lanes/head)

    {   // Qs: 8 rows * 128 floats = 256 float4 slots
        int m = t >> 5, d4 = (t & 31) * 4;
        *(float4*)&Qs[m * 128 + d4] =
            *(const float4*)&g_Q[((size_t)b * NN + n0 + m) * DD + d4];
    }
    w1s[t] = sw1[t];
    if (t < 128) w2s[t] = sw2[t];
    if (t < 16) b1s[t] = sb1[t];
    if (t < 8) b2s[t] = sb2[t];

    float M[8], L[8];
#pragma unroll
    for (int h = 0; h < 8; h++) { M[h] = -1e30f; L[h] = 0.f; }
    float acc0 = 0.f, acc1 = 0.f, acc2 = 0.f, acc3 = 0.f;

#pragma unroll 1
    for (int mc = 0; mc < 8; mc++) {
        __syncthreads();
        // stage K,V chunk: rows m = mc*32 .. +31, 128 floats each
#pragma unroll
        for (int i = 0; i < 4; i++) {
            int e = t + i * 256;                  // 0..1023 float4 slots
            int m = e >> 5, d4 = (e & 31) * 4;
            size_t gb = ((size_t)b * NN + mc * 32 + m) * DD + d4;
            *(float4*)&Ks[m * 132 + d4] = *(const float4*)&g_K[gb];
            *(float4*)&Vs[m * 128 + d4] = *(const float4*)&g_V[gb];
        }
        __syncthreads();

        // ---- scores s[h] for position (n, m = mc*32+lane) ----
        float s[8];
#pragma unroll
        for (int h = 0; h < 8; h++) {
            float4 k0 = *(const float4*)&Ks[lane * 132 + h * 16];
            float4 k1 = *(const float4*)&Ks[lane * 132 + h * 16 + 4];
            float4 k2 = *(const float4*)&Ks[lane * 132 + h * 16 + 8];
            float4 k3 = *(const float4*)&Ks[lane * 132 + h * 16 + 12];
            float4 q0 = *(const float4*)&Qs[w * 128 + h * 16];
            float4 q1 = *(const float4*)&Qs[w * 128 + h * 16 + 4];
            float4 q2 = *(const float4*)&Qs[w * 128 + h * 16 + 8];
            float4 q3 = *(const float4*)&Qs[w * 128 + h * 16 + 12];
            s[h] = q0.x * k0.x + q0.y * k0.y + q0.z * k0.z + q0.w * k0.w
                 + q1.x * k1.x + q1.y * k1.y + q1.z * k1.z + q1.w * k1.w
                 + q2.x * k2.x + q2.y * k2.y + q2.z * k2.z + q2.w * k2.w
                 + q3.x * k3.x + q3.y * k3.y + q3.z * k3.z + q3.w * k3.w;
        }
        // ---- route (coalesced over lanes); pass through to output tail ----
        float r[8];
#pragma unroll
        for (int h = 0; h < 8; h++) {
            size_t ri = (((size_t)h * BB + b) * NN + n) * NN + mc * 32 + lane;
            r[h] = route[ri];
            if (rout) rout[ri] = r[h];
        }

        // ---- score_aggr MLP: 16 -> relu16 -> 8 ----
        float hd[16];
#pragma unroll
        for (int j = 0; j < 16; j++) hd[j] = b1s[j];
#pragma unroll
        for (int i = 0; i < 16; i++) {
            float xi = (i < 8) ? s[i] : r[i - 8];
            float4 wa = *(const float4*)&w1s[i * 16];
            float4 wb = *(const float4*)&w1s[i * 16 + 4];
            float4 wc = *(const float4*)&w1s[i * 16 + 8];
            float4 wd = *(const float4*)&w1s[i * 16 + 12];
            hd[0] += xi * wa.x; hd[1] += xi * wa.y; hd[2] += xi * wa.z; hd[3] += xi * wa.w;
            hd[4] += xi * wb.x; hd[5] += xi * wb.y; hd[6] += xi * wb.z; hd[7] += xi * wb.w;
            hd[8] += xi * wc.x; hd[9] += xi * wc.y; hd[10] += xi * wc.z; hd[11] += xi * wc.w;
            hd[12] += xi * wd.x; hd[13] += xi * wd.y; hd[14] += xi * wd.z; hd[15] += xi * wd.w;
        }
        float a[8];
#pragma unroll
        for (int h = 0; h < 8; h++) a[h] = b2s[h];
#pragma unroll
        for (int j = 0; j < 16; j++) {
            float hj = fmaxf(hd[j], 0.f);
            float4 wa = *(const float4*)&w2s[j * 8];
            float4 wb = *(const float4*)&w2s[j * 8 + 4];
            a[0] += hj * wa.x; a[1] += hj * wa.y; a[2] += hj * wa.z; a[3] += hj * wa.w;
            a[4] += hj * wb.x; a[5] += hj * wb.y; a[6] += hj * wb.z; a[7] += hj * wb.w;
        }

        // ---- online softmax: pipelined butterflies (8 independent chains) ----
        float cm[8];
#pragma unroll
        for (int h = 0; h < 8; h++) cm[h] = a[h];
#pragma unroll
        for (int o = 16; o > 0; o >>= 1)
#pragma unroll
            for (int h = 0; h < 8; h++)
                cm[h] = fmaxf(cm[h], __shfl_xor_sync(0xffffffffu, cm[h], o));
        float cs[8], sc[8];
#pragma unroll
        for (int h = 0; h < 8; h++) {
            float nm = fmaxf(M[h], cm[h]);
            float ev = __expf(a[h] - nm);
            ps[(w * 8 + h) * 33 + lane] = ev;
            cs[h] = ev;
            sc[h] = __expf(M[h] - nm);
            M[h] = nm;
        }
#pragma unroll
        for (int o = 16; o > 0; o >>= 1)
#pragma unroll
            for (int h = 0; h < 8; h++)
                cs[h] += __shfl_xor_sync(0xffffffffu, cs[h], o);
#pragma unroll
        for (int h = 0; h < 8; h++)
            L[h] = L[h] * sc[h] + cs[h];

        float sown;
        SEL8(sc, hme, sown);
        acc0 *= sown; acc1 *= sown; acc2 *= sown; acc3 *= sown;
        __syncwarp();

        // ---- P @ V accumulate (lane owns d = lane*4 .. +3, within head hme) ----
#pragma unroll
        for (int m = 0; m < 32; m++) {
            float p = ps[(w * 8 + hme) * 33 + m];
            float4 v = *(const float4*)&Vs[m * 128 + lane * 4];
            acc0 += p * v.x; acc1 += p * v.y; acc2 += p * v.z; acc3 += p * v.w;
        }
        __syncwarp();
    }
    float Lown;
    SEL8(L, hme, Lown);
    float inv = 1.f / Lown;
    *(float4*)&g_heads[((size_t)b * NN + n) * DD + lane * 4] =
        make_float4(acc0 * inv, acc1 * inv, acc2 * inv, acc3 * inv);
}

// ============ K4: heads @ W_out + h_em -> x0, LN partials[0] ============
__global__ __launch_bounds__(256) void k4_out(const float* __restrict__ Wo,
                                              const float* __restrict__ hem) {
    __shared__ __align__(16) float ws[32 * 128];
    __shared__ __align__(16) float xs[32 * 128];
    __shared__ float red[16];
    int b = blockIdx.y, n0 = blockIdx.x * 32, t = threadIdx.x;
    int w = t >> 5, lane = t & 31;
    const float4* hd4 = (const float4*)(g_heads + ((size_t)b * NN + n0) * DD);
    for (int e = t; e < 1024; e += 256)
        ((float4*)xs)[e] = hd4[e];
    const float* xrow = &xs[(w * 4) * 128];
    float acc[4][4] = {};
    const float4* Wo4 = (const float4*)Wo;
    for (int kc = 0; kc < 4; kc++) {
        __syncthreads();
        for (int e = t; e < 1024; e += 256) {
            int row = e >> 5, c = e & 31;
            ((float4*)ws)[e] = Wo4[(kc * 32 + row) * 32 + c];
        }
        __syncthreads();
#pragma unroll 2
        for (int dl = 0; dl < 32; dl += 4) {
            float4 xv[4];
#pragma unroll
            for (int r = 0; r < 4; r++)
                xv[r] = *(const float4*)&xrow[r * 128 + kc * 32 + dl];
#pragma unroll
            for (int j = 0; j < 4; j++) {
                float4 wv = *(const float4*)&ws[(dl + j) * 128 + lane * 4];
#pragma unroll
                for (int r = 0; r < 4; r++) {
                    float xj = (j == 0) ? xv[r].x : (j == 1) ? xv[r].y
                             : (j == 2) ? xv[r].z : xv[r].w;
                    acc[r][0] += xj * wv.x; acc[r][1] += xj * wv.y;
                    acc[r][2] += xj * wv.z; acc[r][3] += xj * wv.w;
                }
            }
        }
    }
    float ls = 0.f, lq = 0.f;
#pragma unroll
    for (int r = 0; r < 4; r++) {
        size_t base = ((size_t)b * NN + n0 + w * 4 + r) * DD + lane * 4;
        float4 he = *(const float4*)&hem[base];
        float v0 = acc[r][0] + he.x, v1 = acc[r][1] + he.y;
        float v2 = acc[r][2] + he.z, v3 = acc[r][3] + he.w;
        *(float4*)&g_x0[base] = make_float4(v0, v1, v2, v3);
        ls += v0 + v1 + v2 + v3;
        lq += v0 * v0 + v1 * v1 + v2 * v2 + v3 * v3;
    }
#pragma unroll
    for (int o = 16; o > 0; o >>= 1) {
        ls += __shfl_xor_sync(0xffffffffu, ls, o);
        lq += __shfl_xor_sync(0xffffffffu, lq, o);
    }
    if (lane == 0) { red[w] = ls; red[8 + w] = lq; }
    __syncthreads();
    if (t == 0) {
        float s = 0.f, q = 0.f;
        for (int i = 0; i < 8; i++) { s += red[i]; q += red[8 + i]; }
        g_ps[0][b * 8 + blockIdx.x] = s;
        g_pq[0][b * 8 + blockIdx.x] = q;
    }
}

// ============ K6: x = LN(x0); hdn = relu(x @ ff_w1) ============
__global__ __launch_bounds__(256) void k6_ff1(const float* __restrict__ w1) {
    __shared__ __align__(16) float ws[32 * 128];
    __shared__ __align__(16) float xs[32 * 128];
    __shared__ float s_mu, s_iv;
    int b = blockIdx.y, n0 = blockIdx.x * 32, t = threadIdx.x;
    int w = t >> 5, lane = t & 31;
    if (t == 0) ln_finalize(0, b, (float*)&s_mu, (float*)&s_iv);
    __syncthreads();
    float mu = s_mu, iv = s_iv;
    const float4* x04 = (const float4*)(g_x0 + ((size_t)b * NN + n0) * DD);
    for (int e = t; e < 1024; e += 256) {
        float4 v = x04[e];
        v.x = (v.x - mu) * iv; v.y = (v.y - mu) * iv;
        v.z = (v.z - mu) * iv; v.w = (v.w - mu) * iv;
        ((float4*)xs)[e] = v;
    }
    const float* xrow = &xs[(w * 4) * 128];
    const float4* w14 = (const float4*)w1;
    for (int ft = 0; ft < 4; ft++) {
        float acc[4][4] = {};
        for (int dc = 0; dc < 4; dc++) {
            __syncthreads();
            for (int e = t; e < 1024; e += 256) {
                int row = e >> 5, c = e & 31;
                ((float4*)ws)[e] = w14[(dc * 32 + row) * 128 + ft * 32 + c];
            }
            __syncthreads();
#pragma unroll 2
            for (int dl = 0; dl < 32; dl += 4) {
                float4 xv[4];
#pragma unroll
                for (int r = 0; r < 4; r++)
                    xv[r] = *(const float4*)&xrow[r * 128 + dc * 32 + dl];
#pragma unroll
                for (int j = 0; j < 4; j++) {
                    float4 wv = *(const float4*)&ws[(dl + j) * 128 + lane * 4];
#pragma unroll
                    for (int r = 0; r < 4; r++) {
                        float xj = (j == 0) ? xv[r].x : (j == 1) ? xv[r].y
                                 : (j == 2) ? xv[r].z : xv[r].w;
                        acc[r][0] += xj * wv.x; acc[r][1] += xj * wv.y;
                        acc[r][2] += xj * wv.z; acc[r][3] += xj * wv.w;
                    }
                }
            }
        }
#pragma unroll
        for (int r = 0; r < 4; r++)
            *(float4*)&g_hdn[((size_t)b * NN + n0 + w * 4 + r) * FF + ft * 128 + lane * 4] =
                make_float4(fmaxf(acc[r][0], 0.f), fmaxf(acc[r][1], 0.f),
                            fmaxf(acc[r][2], 0.f), fmaxf(acc[r][3], 0.f));
    }
}

// ============ K7: y0 = hdn @ ff_w2 + x, LN partials[1] ============
__global__ __launch_bounds__(256) void k7_ff2(const float* __restrict__ w2) {
    __shared__ __align__(16) float ws[32 * 128];
    __shared__ __align__(16) float hs[32 * 32];
    __shared__ float red[16];
    __shared__ float s_mu, s_iv;
    int b = blockIdx.y, n0 = blockIdx.x * 32, t = threadIdx.x;
    int w = t >> 5, lane = t & 31;
    if (t == 0) ln_finalize(0, b, (float*)&s_mu, (float*)&s_iv);
    float acc[4][4] = {};
    const float4* w24 = (const float4*)w2;
    const float4* hdn4 = (const float4*)g_hdn;
    for (int kc = 0; kc < 16; kc++) {
        __syncthreads();
        for (int e = t; e < 1024; e += 256) {
            int row = e >> 5, c = e & 31;
            ((float4*)ws)[e] = w24[(kc * 32 + row) * 32 + c];
        }
        {
            int row = t >> 3, c = t & 7;      // 256 float4 slots, 1/thread
            ((float4*)hs)[t] = hdn4[((size_t)b * NN + n0 + row) * (FF / 4) + kc * 8 + c];
        }
        __syncthreads();
#pragma unroll 2
        for (int dl = 0; dl < 32; dl += 4) {
            float4 xv[4];
#pragma unroll
            for (int r = 0; r < 4; r++)
                xv[r] = *(const float4*)&hs[(w * 4 + r) * 32 + dl];
#pragma unroll
            for (int j = 0; j < 4; j++) {
                float4 wv = *(const float4*)&ws[(dl + j) * 128 + lane * 4];
#pragma unroll
                for (int r = 0; r < 4; r++) {
                    float xj = (j == 0) ? xv[r].x : (j == 1) ? xv[r].y
                             : (j == 2) ? xv[r].z : xv[r].w;
                    acc[r][0] += xj * wv.x; acc[r][1] += xj * wv.y;
                    acc[r][2] += xj * wv.z; acc[r][3] += xj * wv.w;
                }
            }
        }
    }
    float mu = s_mu, iv = s_iv;
    float ls = 0.f, lq = 0.f;
#pragma unroll
    for (int r = 0; r < 4; r++) {
        size_t base = ((size_t)b * NN + n0 + w * 4 + r) * DD + lane * 4;
        float4 xv = *(const float4*)&g_x0[base];
        float v0 = acc[r][0] + (xv.x - mu) * iv;
        float v1 = acc[r][1] + (xv.y - mu) * iv;
        float v2 = acc[r][2] + (xv.z - mu) * iv;
        float v3 = acc[r][3] + (xv.w - mu) * iv;
        *(float4*)&g_y0[base] = make_float4(v0, v1, v2, v3);
        ls += v0 + v1 + v2 + v3;
        lq += v0 * v0 + v1 * v1 + v2 * v2 + v3 * v3;
    }
#pragma unroll
    for (int o = 16; o > 0; o >>= 1) {
        ls += __shfl_xor_sync(0xffffffffu, ls, o);
        lq += __shfl_xor_sync(0xffffffffu, lq, o);
    }
    if (lane == 0) { red[w] = ls; red[8 + w] = lq; }
    __syncthreads();
    if (t == 0) {
        float s = 0.f, q = 0.f;
        for (int i = 0; i < 8; i++) { s += red[i]; q += red[8 + i]; }
        g_ps[1][b * 8 + blockIdx.x] = s;
        g_pq[1][b * 8 + blockIdx.x] = q;
    }
}

// ============ K8: out1 = LN(y0) ============
__global__ __launch_bounds__(256) void k8_norm(float* __restrict__ out) {
    __shared__ float s_mu, s_iv;
    int i = blockIdx.x * 256 + threadIdx.x;   // 524288 float4; one b per block
    int b = i >> 13;
    if (threadIdx.x == 0) ln_finalize(1, b, (float*)&s_mu, (float*)&s_iv);
    __syncthreads();
    float mu = s_mu, iv = s_iv;
    float4 v = ((const float4*)g_y0)[i];
    v.x = (v.x - mu) * iv; v.y = (v.y - mu) * iv;
    v.z = (v.z - mu) * iv; v.w = (v.w - mu) * iv;
    ((float4*)out)[i] = v;
}

// ============ launcher ============
extern "C" void kernel_launch(void* const* d_in, const int* in_sizes, int n_in,
                              void* d_out, int out_size) {
    const float* hem = (const float*)d_in[0];
    const float* route = (const float*)d_in[1];
    const float* Wq = (const float*)d_in[2];
    const float* Wk = (const float*)d_in[3];
    const float* Wv = (const float*)d_in[4];
    const float* Wo = (const float*)d_in[5];
    const float* sw1 = (const float*)d_in[6];
    const float* sb1 = (const float*)d_in[7];
    const float* sw2 = (const float*)d_in[8];
    const float* sb2 = (const float*)d_in[9];
    const float* fw1 = (const float*)d_in[10];
    const float* fw2 = (const float*)d_in[11];
    float* out = (float*)d_out;

    const long long OUT1 = (long long)BB * NN * DD;        // 2097152
    const long long ROUTE = (long long)HH * BB * NN * NN;  // 33554432
    float* rout = ((long long)out_size >= OUT1 + ROUTE) ? (out + OUT1) : (float*)0;

    dim3 g8(8, BB);
    dim3 g32(32, BB);

    k1_qkv<<<g8, 256>>>(hem, Wq, Wk, Wv);
    k2_flash<<<g32, 256>>>(route, sw1, sb1, sw2, sb2, rout);
    k4_out<<<g8, 256>>>(Wo, hem);
    k6_ff1<<<g8, 256>>>(fw1);
    k7_ff2<<<g8, 256>>>(fw2);
    k8_norm<<<2048, 256>>>(out);
}

// round 14
// speedup vs baseline: 4.5160x; 1.1364x over previous
#include <cuda_runtime.h>
#include <math.h>

#define BB 64
#define NN 256
#define DD 128
#define HH 8
#define FF 512
#define EPSV 1e-5

// ------- scratch (device globals; no allocations anywhere) -------
__device__ float g_Q[BB * NN * DD];
__device__ float g_K[BB * NN * DD];
__device__ float g_V[BB * NN * DD];
__device__ float g_heads[BB * NN * DD];
__device__ float g_x0[BB * NN * DD];
__device__ float g_hdn[BB * NN * FF];
__device__ float g_y0[BB * NN * DD];
__device__ float g_ps[2][BB * 8];
__device__ float g_pq[2][BB * 8];

// select arr[idx] for idx in 0..7 without dynamic indexing (no local-mem spill)
#define SEL8(arr, idx, out) do {                                   \
    float _s0 = ((idx) & 1) ? (arr)[1] : (arr)[0];                 \
    float _s1 = ((idx) & 1) ? (arr)[3] : (arr)[2];                 \
    float _s2 = ((idx) & 1) ? (arr)[5] : (arr)[4];                 \
    float _s3 = ((idx) & 1) ? (arr)[7] : (arr)[6];                 \
    float _t0 = ((idx) & 2) ? _s1 : _s0;                           \
    float _t1 = ((idx) & 2) ? _s3 : _s2;                           \
    (out) = ((idx) & 4) ? _t1 : _t0;                               \
} while (0)

// finalize LN stats for batch b from 8 partials (ddof=1), double precision
__device__ __forceinline__ void ln_finalize(int which, int b, float* mu, float* iv) {
    double s = 0.0, q = 0.0;
#pragma unroll
    for (int i = 0; i < 8; i++) {
        s += (double)g_ps[which][b * 8 + i];
        q += (double)g_pq[which][b * 8 + i];
    }
    double n = (double)(NN * DD);
    double mean = s / n;
    double var = (q - s * s / n) / (n - 1.0);
    *mu = (float)mean;
    *iv = (float)(1.0 / sqrt(var + EPSV));
}

// 4-row x 4-col x 4-k micro-tile (xv broadcast, wv strided conflict-free)
#define MICRO44(acc, xrow, xstride, kofs, ws, lane)                         \
    do {                                                                    \
        float4 xv[4];                                                       \
        _Pragma("unroll")                                                   \
        for (int _r = 0; _r < 4; _r++)                                      \
            xv[_r] = *(const float4*)&(xrow)[_r * (xstride) + (kofs)];      \
        _Pragma("unroll")                                                   \
        for (int _j = 0; _j < 4; _j++) {                                    \
            float4 wv = *(const float4*)&(ws)[(dl + _j) * 128 + (lane) * 4];\
            _Pragma("unroll")                                               \
            for (int _r = 0; _r < 4; _r++) {                                \
                float xj = (_j == 0) ? xv[_r].x : (_j == 1) ? xv[_r].y      \
                         : (_j == 2) ? xv[_r].z : xv[_r].w;                 \
                acc[_r][0] += xj * wv.x; acc[_r][1] += xj * wv.y;           \
                acc[_r][2] += xj * wv.z; acc[_r][3] += xj * wv.w;           \
            }                                                               \
        }                                                                   \
    } while (0)

// ============ K1: Q/K/V projections (32 rows/block, 4x4 tile, prefetch) ====
__global__ __launch_bounds__(256) void k1_qkv(const float* __restrict__ hem,
                                              const float* __restrict__ Wq,
                                              const float* __restrict__ Wk,
                                              const float* __restrict__ Wv) {
    __shared__ __align__(16) float ws[32 * 128];
    __shared__ __align__(16) float xs[32 * 128];
    int b = blockIdx.y, n0 = blockIdx.x * 32, t = threadIdx.x;
    int w = t >> 5, lane = t & 31;

    // preload stage 0 weights (wi=0, dc=0) before xs staging LDGs
    float4 pf[4];
#pragma unroll
    for (int i = 0; i < 4; i++) {
        int e = t + i * 256, h = e >> 7, dl = (e >> 2) & 31, k4 = e & 3;
        pf[i] = ((const float4*)Wq)[h * 512 + dl * 4 + k4];
    }
    const float4* hem4 = (const float4*)(hem + ((size_t)b * NN + n0) * DD);
    for (int e = t; e < 1024; e += 256)
        ((float4*)xs)[e] = hem4[e];
    const float* xrow = &xs[(w * 4) * 128];

    float acc[4][4] = {};
    for (int s = 0; s < 12; s++) {
        int wi = s >> 2, dc = s & 3;
        __syncthreads();
#pragma unroll
        for (int i = 0; i < 4; i++) {
            int e = t + i * 256, h = e >> 7, dl = (e >> 2) & 31, k4 = e & 3;
            ((float4*)ws)[dl * 32 + h * 4 + k4] = pf[i];
        }
        __syncthreads();
        if (s < 11) {
            int s2 = s + 1, wi2 = s2 >> 2, dc2 = s2 & 3;
            const float4* W4 = (wi2 == 0) ? (const float4*)Wq
                             : (wi2 == 1) ? (const float4*)Wk : (const float4*)Wv;
#pragma unroll
            for (int i = 0; i < 4; i++) {
                int e = t + i * 256, h = e >> 7, dl = (e >> 2) & 31, k4 = e & 3;
                pf[i] = W4[h * 512 + (dc2 * 32 + dl) * 4 + k4];
            }
        }
#pragma unroll 2
        for (int dl = 0; dl < 32; dl += 4)
            MICRO44(acc, xrow, 128, dc * 32 + dl, ws, lane);
        if (dc == 3) {
            float* O = (wi == 0) ? g_Q : (wi == 1) ? g_K : g_V;
#pragma unroll
            for (int r = 0; r < 4; r++) {
                *(float4*)&O[((size_t)b * NN + n0 + w * 4 + r) * DD + lane * 4] =
                    make_float4(acc[r][0], acc[r][1], acc[r][2], acc[r][3]);
                acc[r][0] = acc[r][1] = acc[r][2] = acc[r][3] = 0.f;
            }
        }
    }
}

// ==== K2 (flash): scores + score_aggr MLP + online softmax + P@V -> heads ====
__global__ __launch_bounds__(256) void k2_flash(const float* __restrict__ route,
                                                const float* __restrict__ sw1,
                                                const float* __restrict__ sb1,
                                                const float* __restrict__ sw2,
                                                const float* __restrict__ sb2,
                                                float* __restrict__ rout) {
    __shared__ __align__(16) float Qs[8 * 128];
    __shared__ __align__(16) float Ks[32 * 132];
    __shared__ __align__(16) float Vs[32 * 128];
    __shared__ float ps[8 * 8 * 33];
    __shared__ __align__(16) float w1s[256];
    __shared__ __align__(16) float w2s[128];
    __shared__ float b1s[16], b2s[8];

    int b = blockIdx.y, n0 = blockIdx.x * 8, t = threadIdx.x;
    int w = t >> 5, lane = t & 31;
    int n = n0 + w;
    int hme = lane >> 2;

    {
        int m = t >> 5, d4 = (t & 31) * 4;
        *(float4*)&Qs[m * 128 + d4] =
            *(const float4*)&g_Q[((size_t)b * NN + n0 + m) * DD + d4];
    }
    w1s[t] = sw1[t];
    if (t < 128) w2s[t] = sw2[t];
    if (t < 16) b1s[t] = sb1[t];
    if (t < 8) b2s[t] = sb2[t];

    float M[8], L[8];   // L = PER-LANE partial expsum (summed across lanes at end)
#pragma unroll
    for (int h = 0; h < 8; h++) { M[h] = -1e30f; L[h] = 0.f; }
    float acc0 = 0.f, acc1 = 0.f, acc2 = 0.f, acc3 = 0.f;

#pragma unroll 1
    for (int mc = 0; mc < 8; mc++) {
        __syncthreads();
#pragma unroll
        for (int i = 0; i < 4; i++) {
            int e = t + i * 256;
            int m = e >> 5, d4 = (e & 31) * 4;
            size_t gb = ((size_t)b * NN + mc * 32 + m) * DD + d4;
            *(float4*)&Ks[m * 132 + d4] = *(const float4*)&g_K[gb];
            *(float4*)&Vs[m * 128 + d4] = *(const float4*)&g_V[gb];
        }
        __syncthreads();

        // ---- scores s[h] for position (n, m = mc*32+lane) ----
        float s[8];
#pragma unroll
        for (int h = 0; h < 8; h++) {
            float4 k0 = *(const float4*)&Ks[lane * 132 + h * 16];
            float4 k1 = *(const float4*)&Ks[lane * 132 + h * 16 + 4];
            float4 k2 = *(const float4*)&Ks[lane * 132 + h * 16 + 8];
            float4 k3 = *(const float4*)&Ks[lane * 132 + h * 16 + 12];
            float4 q0 = *(const float4*)&Qs[w * 128 + h * 16];
            float4 q1 = *(const float4*)&Qs[w * 128 + h * 16 + 4];
            float4 q2 = *(const float4*)&Qs[w * 128 + h * 16 + 8];
            float4 q3 = *(const float4*)&Qs[w * 128 + h * 16 + 12];
            s[h] = q0.x * k0.x + q0.y * k0.y + q0.z * k0.z + q0.w * k0.w
                 + q1.x * k1.x + q1.y * k1.y + q1.z * k1.z + q1.w * k1.w
                 + q2.x * k2.x + q2.y * k2.y + q2.z * k2.z + q2.w * k2.w
                 + q3.x * k3.x + q3.y * k3.y + q3.z * k3.z + q3.w * k3.w;
        }
        // ---- route passthrough ----
        float r[8];
#pragma unroll
        for (int h = 0; h < 8; h++) {
            size_t ri = (((size_t)h * BB + b) * NN + n) * NN + mc * 32 + lane;
            r[h] = route[ri];
            if (rout) rout[ri] = r[h];
        }

        // ---- score_aggr MLP: 16 -> relu16 -> 8 ----
        float hd[16];
#pragma unroll
        for (int j = 0; j < 16; j++) hd[j] = b1s[j];
#pragma unroll
        for (int i = 0; i < 16; i++) {
            float xi = (i < 8) ? s[i] : r[i - 8];
            float4 wa = *(const float4*)&w1s[i * 16];
            float4 wb = *(const float4*)&w1s[i * 16 + 4];
            float4 wc = *(const float4*)&w1s[i * 16 + 8];
            float4 wd = *(const float4*)&w1s[i * 16 + 12];
            hd[0] += xi * wa.x; hd[1] += xi * wa.y; hd[2] += xi * wa.z; hd[3] += xi * wa.w;
            hd[4] += xi * wb.x; hd[5] += xi * wb.y; hd[6] += xi * wb.z; hd[7] += xi * wb.w;
            hd[8] += xi * wc.x; hd[9] += xi * wc.y; hd[10] += xi * wc.z; hd[11] += xi * wc.w;
            hd[12] += xi * wd.x; hd[13] += xi * wd.y; hd[14] += xi * wd.z; hd[15] += xi * wd.w;
        }
        float a[8];
#pragma unroll
        for (int h = 0; h < 8; h++) a[h] = b2s[h];
#pragma unroll
        for (int j = 0; j < 16; j++) {
            float hj = fmaxf(hd[j], 0.f);
            float4 wa = *(const float4*)&w2s[j * 8];
            float4 wb = *(const float4*)&w2s[j * 8 + 4];
            a[0] += hj * wa.x; a[1] += hj * wa.y; a[2] += hj * wa.z; a[3] += hj * wa.w;
            a[4] += hj * wb.x; a[5] += hj * wb.y; a[6] += hj * wb.z; a[7] += hj * wb.w;
        }

        // ---- online softmax: max butterfly only (sum deferred to end) ----
        float cm[8];
#pragma unroll
        for (int h = 0; h < 8; h++) cm[h] = a[h];
#pragma unroll
        for (int o = 16; o > 0; o >>= 1)
#pragma unroll
            for (int h = 0; h < 8; h++)
                cm[h] = fmaxf(cm[h], __shfl_xor_sync(0xffffffffu, cm[h], o));
        float sc[8];
#pragma unroll
        for (int h = 0; h < 8; h++) {
            float nm = fmaxf(M[h], cm[h]);
            float ev = __expf(a[h] - nm);
            ps[(w * 8 + h) * 33 + lane] = ev;
            sc[h] = __expf(M[h] - nm);      // warp-uniform
            L[h] = L[h] * sc[h] + ev;       // per-lane partial
            M[h] = nm;
        }
        float sown;
        SEL8(sc, hme, sown);
        acc0 *= sown; acc1 *= sown; acc2 *= sown; acc3 *= sown;
        __syncwarp();

        // ---- P @ V accumulate ----
#pragma unroll
        for (int m = 0; m < 32; m++) {
            float p = ps[(w * 8 + hme) * 33 + m];
            float4 v = *(const float4*)&Vs[m * 128 + lane * 4];
            acc0 += p * v.x; acc1 += p * v.y; acc2 += p * v.z; acc3 += p * v.w;
        }
        __syncwarp();
    }
    // final cross-lane sum of L partials (once)
#pragma unroll
    for (int o = 16; o > 0; o >>= 1)
#pragma unroll
        for (int h = 0; h < 8; h++)
            L[h] += __shfl_xor_sync(0xffffffffu, L[h], o);
    float Lown;
    SEL8(L, hme, Lown);
    float inv = 1.f / Lown;
    *(float4*)&g_heads[((size_t)b * NN + n) * DD + lane * 4] =
        make_float4(acc0 * inv, acc1 * inv, acc2 * inv, acc3 * inv);
}

// ============ K4: heads @ W_out + h_em -> x0, LN partials[0], prefetch ======
__global__ __launch_bounds__(256) void k4_out(const float* __restrict__ Wo,
                                              const float* __restrict__ hem) {
    __shared__ __align__(16) float ws[32 * 128];
    __shared__ __align__(16) float xs[32 * 128];
    __shared__ float red[16];
    int b = blockIdx.y, n0 = blockIdx.x * 32, t = threadIdx.x;
    int w = t >> 5, lane = t & 31;
    const float4* Wo4 = (const float4*)Wo;
    float4 pf[4];
#pragma unroll
    for (int i = 0; i < 4; i++)
        pf[i] = Wo4[(w + i * 8) * 32 + lane];
    const float4* hd4 = (const float4*)(g_heads + ((size_t)b * NN + n0) * DD);
    for (int e = t; e < 1024; e += 256)
        ((float4*)xs)[e] = hd4[e];
    const float* xrow = &xs[(w * 4) * 128];
    float acc[4][4] = {};
    for (int kc = 0; kc < 4; kc++) {
        __syncthreads();
#pragma unroll
        for (int i = 0; i < 4; i++)
            ((float4*)ws)[(w + i * 8) * 32 + lane] = pf[i];
        __syncthreads();
        if (kc < 3) {
#pragma unroll
            for (int i = 0; i < 4; i++)
                pf[i] = Wo4[((kc + 1) * 32 + w + i * 8) * 32 + lane];
        }
#pragma unroll 2
        for (int dl = 0; dl < 32; dl += 4)
            MICRO44(acc, xrow, 128, kc * 32 + dl, ws, lane);
    }
    float ls = 0.f, lq = 0.f;
#pragma unroll
    for (int r = 0; r < 4; r++) {
        size_t base = ((size_t)b * NN + n0 + w * 4 + r) * DD + lane * 4;
        float4 he = *(const float4*)&hem[base];
        float v0 = acc[r][0] + he.x, v1 = acc[r][1] + he.y;
        float v2 = acc[r][2] + he.z, v3 = acc[r][3] + he.w;
        *(float4*)&g_x0[base] = make_float4(v0, v1, v2, v3);
        ls += v0 + v1 + v2 + v3;
        lq += v0 * v0 + v1 * v1 + v2 * v2 + v3 * v3;
    }
#pragma unroll
    for (int o = 16; o > 0; o >>= 1) {
        ls += __shfl_xor_sync(0xffffffffu, ls, o);
        lq += __shfl_xor_sync(0xffffffffu, lq, o);
    }
    if (lane == 0) { red[w] = ls; red[8 + w] = lq; }
    __syncthreads();
    if (t == 0) {
        float s = 0.f, q = 0.f;
        for (int i = 0; i < 8; i++) { s += red[i]; q += red[8 + i]; }
        g_ps[0][b * 8 + blockIdx.x] = s;
        g_pq[0][b * 8 + blockIdx.x] = q;
    }
}

// ============ K6: x = LN(x0); hdn = relu(x @ ff_w1), prefetch ============
__global__ __launch_bounds__(256) void k6_ff1(const float* __restrict__ w1) {
    __shared__ __align__(16) float ws[32 * 128];
    __shared__ __align__(16) float xs[32 * 128];
    __shared__ float s_mu, s_iv;
    int b = blockIdx.y, n0 = blockIdx.x * 32, t = threadIdx.x;
    int w = t >> 5, lane = t & 31;
    const float4* w14 = (const float4*)w1;
    float4 pf[4];
#pragma unroll
    for (int i = 0; i < 4; i++)
        pf[i] = w14[(w + i * 8) * 128 + lane];      // ft=0, dc=0
    if (t == 0) ln_finalize(0, b, (float*)&s_mu, (float*)&s_iv);
    __syncthreads();
    float mu = s_mu, iv = s_iv;
    const float4* x04 = (const float4*)(g_x0 + ((size_t)b * NN + n0) * DD);
    for (int e = t; e < 1024; e += 256) {
        float4 v = x04[e];
        v.x = (v.x - mu) * iv; v.y = (v.y - mu) * iv;
        v.z = (v.z - mu) * iv; v.w = (v.w - mu) * iv;
        ((float4*)xs)[e] = v;
    }
    const float* xrow = &xs[(w * 4) * 128];
    float acc[4][4] = {};
    for (int s = 0; s < 16; s++) {
        int ft = s >> 2, dc = s & 3;
        __syncthreads();
#pragma unroll
        for (int i = 0; i < 4; i++)
            ((float4*)ws)[(w + i * 8) * 32 + lane] = pf[i];
        __syncthreads();
        if (s < 15) {
            int s2 = s + 1, ft2 = s2 >> 2, dc2 = s2 & 3;
#pragma unroll
            for (int i = 0; i < 4; i++)
                pf[i] = w14[(dc2 * 32 + w + i * 8) * 128 + ft2 * 32 + lane];
        }
#pragma unroll 2
        for (int dl = 0; dl < 32; dl += 4)
            MICRO44(acc, xrow, 128, dc * 32 + dl, ws, lane);
        if (dc == 3) {
#pragma unroll
            for (int r = 0; r < 4; r++) {
                *(float4*)&g_hdn[((size_t)b * NN + n0 + w * 4 + r) * FF + ft * 128 + lane * 4] =
                    make_float4(fmaxf(acc[r][0], 0.f), fmaxf(acc[r][1], 0.f),
                                fmaxf(acc[r][2], 0.f), fmaxf(acc[r][3], 0.f));
                acc[r][0] = acc[r][1] = acc[r][2] = acc[r][3] = 0.f;
            }
        }
    }
}

// ============ K7: y0 = hdn @ ff_w2 + x, LN partials[1], prefetch ============
__global__ __launch_bounds__(256) void k7_ff2(const float* __restrict__ w2) {
    __shared__ __align__(16) float ws[32 * 128];
    __shared__ __align__(16) float hs[32 * 32];
    __shared__ float red[16];
    __shared__ float s_mu, s_iv;
    int b = blockIdx.y, n0 = blockIdx.x * 32, t = threadIdx.x;
    int w = t >> 5, lane = t & 31;
    const float4* w24 = (const float4*)w2;
    const float4* hdn4 = (const float4*)g_hdn;
    int hrow = t >> 3, hc = t & 7;
    float4 pfw[4], pfh;
#pragma unroll
    for (int i = 0; i < 4; i++)
        pfw[i] = w24[(w + i * 8) * 32 + lane];
    pfh = hdn4[((size_t)b * NN + n0 + hrow) * (FF / 4) + hc];
    if (t == 0) ln_finalize(0, b, (float*)&s_mu, (float*)&s_iv);
    float acc[4][4] = {};
    for (int kc = 0; kc < 16; kc++) {
        __syncthreads();
#pragma unroll
        for (int i = 0; i < 4; i++)
            ((float4*)ws)[(w + i * 8) * 32 + lane] = pfw[i];
        ((float4*)hs)[t] = pfh;
        __syncthreads();
        if (kc < 15) {
#pragma unroll
            for (int i = 0; i < 4; i++)
                pfw[i] = w24[((kc + 1) * 32 + w + i * 8) * 32 + lane];
            pfh = hdn4[((size_t)b * NN + n0 + hrow) * (FF / 4) + (kc + 1) * 8 + hc];
        }
#pragma unroll 2
        for (int dl = 0; dl < 32; dl += 4)
            MICRO44(acc, &hs[(w * 4) * 32], 32, dl, ws, lane);
    }
    float mu = s_mu, iv = s_iv;
    float ls = 0.f, lq = 0.f;
#pragma unroll
    for (int r = 0; r < 4; r++) {
        size_t base = ((size_t)b * NN + n0 + w * 4 + r) * DD + lane * 4;
        float4 xv = *(const float4*)&g_x0[base];
        float v0 = acc[r][0] + (xv.x - mu) * iv;
        float v1 = acc[r][1] + (xv.y - mu) * iv;
        float v2 = acc[r][2] + (xv.z - mu) * iv;
        float v3 = acc[r][3] + (xv.w - mu) * iv;
        *(float4*)&g_y0[base] = make_float4(v0, v1, v2, v3);
        ls += v0 + v1 + v2 + v3;
        lq += v0 * v0 + v1 * v1 + v2 * v2 + v3 * v3;
    }
#pragma unroll
    for (int o = 16; o > 0; o >>= 1) {
        ls += __shfl_xor_sync(0xffffffffu, ls, o);
        lq += __shfl_xor_sync(0xffffffffu, lq, o);
    }
    if (lane == 0) { red[w] = ls; red[8 + w] = lq; }
    __syncthreads();
    if (t == 0) {
        float s = 0.f, q = 0.f;
        for (int i = 0; i < 8; i++) { s += red[i]; q += red[8 + i]; }
        g_ps[1][b * 8 + blockIdx.x] = s;
        g_pq[1][b * 8 + blockIdx.x] = q;
    }
}

// ============ K8: out1 = LN(y0) ============
__global__ __launch_bounds__(256) void k8_norm(float* __restrict__ out) {
    __shared__ float s_mu, s_iv;
    int i = blockIdx.x * 256 + threadIdx.x;
    int b = i >> 13;
    if (threadIdx.x == 0) ln_finalize(1, b, (float*)&s_mu, (float*)&s_iv);
    __syncthreads();
    float mu = s_mu, iv = s_iv;
    float4 v = ((const float4*)g_y0)[i];
    v.x = (v.x - mu) * iv; v.y = (v.y - mu) * iv;
    v.z = (v.z - mu) * iv; v.w = (v.w - mu) * iv;
    ((float4*)out)[i] = v;
}

// ============ launcher ============
extern "C" void kernel_launch(void* const* d_in, const int* in_sizes, int n_in,
                              void* d_out, int out_size) {
    const float* hem = (const float*)d_in[0];
    const float* route = (const float*)d_in[1];
    const float* Wq = (const float*)d_in[2];
    const float* Wk = (const float*)d_in[3];
    const float* Wv = (const float*)d_in[4];
    const float* Wo = (const float*)d_in[5];
    const float* sw1 = (const float*)d_in[6];
    const float* sb1 = (const float*)d_in[7];
    const float* sw2 = (const float*)d_in[8];
    const float* sb2 = (const float*)d_in[9];
    const float* fw1 = (const float*)d_in[10];
    const float* fw2 = (const float*)d_in[11];
    float* out = (float*)d_out;

    const long long OUT1 = (long long)BB * NN * DD;        // 2097152
    const long long ROUTE = (long long)HH * BB * NN * NN;  // 33554432
    float* rout = ((long long)out_size >= OUT1 + ROUTE) ? (out + OUT1) : (float*)0;

    dim3 g8(8, BB);
    dim3 g32(32, BB);

    k1_qkv<<<g8, 256>>>(hem, Wq, Wk, Wv);
    k2_flash<<<g32, 256>>>(route, sw1, sb1, sw2, sb2, rout);
    k4_out<<<g8, 256>>>(Wo, hem);
    k6_ff1<<<g8, 256>>>(fw1);
    k7_ff2<<<g8, 256>>>(fw2);
    k8_norm<<<2048, 256>>>(out);
}